// round 15
// baseline (speedup 1.0000x reference)
#include <cuda_runtime.h>
#include <math.h>
#include <float.h>
#include <stdint.h>

#define B_    16
#define NPTS  4096

// ---------------- scratch (static device globals) ---------------------------------
__device__ float g_h1[(size_t)B_ * 64  * NPTS];
__device__ float g_h2[(size_t)B_ * 128 * NPTS];
__device__ float g_h3[(size_t)B_ * 256 * NPTS];
__device__ float g_h3t[(size_t)B_ * NPTS * 256];   // [b][n][c]
__device__ float g_h4[(size_t)B_ * 512 * NPTS];
__device__ float g_h5[(size_t)B_ * 256 * NPTS];
__device__ float g_h6[(size_t)B_ * 128 * NPTS];
__device__ float g_w8t[(size_t)256 * 256 * 256];   // [w][c][o]
__device__ float g_P8[(size_t)32 * 256 * 512];     // split-K partials for conv8 (32 chunks)
__device__ float g_y8[256 * 512];                  // conv8 out, [o][b*32+h]
__device__ float g_y9[B_ * 512];
__device__ float g_gcon[B_ * 512];
__device__ int   g_idx[B_ * 256 * 32];
__device__ float g_scale[6 * 512];
__device__ float g_shift[6 * 512];
__device__ float g_part[512 * B_ * 2];             // stats partials [c][b][2] (conv1)
__device__ int   g_cnt[512];                       // zero-init; reset by finalizer
__device__ float g_part2[(size_t)512 * 1024 * 2];  // epilogue stats partials [c][slot][2]

__device__ __forceinline__ float f2tf32f(float f) {
    uint32_t u;
    asm("cvt.rna.tf32.f32 %0, %1;" : "=r"(u) : "f"(f));
    return __uint_as_float(u);
}

__device__ __forceinline__ void mma_tf32(float* d, const uint32_t* a, const uint32_t* b) {
    asm volatile(
        "mma.sync.aligned.m16n8k8.row.col.f32.tf32.tf32.f32 "
        "{%0,%1,%2,%3}, {%4,%5,%6,%7}, {%8,%9}, {%0,%1,%2,%3};"
        : "+f"(d[0]), "+f"(d[1]), "+f"(d[2]), "+f"(d[3])
        : "r"(a[0]), "r"(a[1]), "r"(a[2]), "r"(a[3]), "r"(b[0]), "r"(b[1]));
}

__device__ __forceinline__ void bn4(float4& v, float sc, float sf, int relu) {
    v.x = v.x * sc + sf; v.y = v.y * sc + sf;
    v.z = v.z * sc + sf; v.w = v.w * sc + sf;
    if (relu) {
        v.x = fmaxf(v.x, 0.f); v.y = fmaxf(v.y, 0.f);
        v.z = fmaxf(v.z, 0.f); v.w = fmaxf(v.w, 0.f);
    }
}

// ---------------- fp32 SGEMM 64x64 (conv1 only: K=4) --------------------------------
__global__ void gemm_f32(const float* __restrict__ X, const float* __restrict__ W,
                         const float* __restrict__ bias, float* __restrict__ Y,
                         int O, int K, int N, int ldw,
                         const float* __restrict__ bnS, const float* __restrict__ bnF,
                         int relu)
{
    __shared__ float As[16][66];
    __shared__ float Bs[16][64];

    int b  = blockIdx.z;
    int o0 = blockIdx.y * 64;
    int n0 = blockIdx.x * 64;
    const float* Xb = X + (size_t)b * K * N;

    int tid = threadIdx.x;
    int tm  = tid >> 4;
    int tn  = tid & 15;

    float acc[4][4] = {};

    for (int k0 = 0; k0 < K; k0 += 16) {
        #pragma unroll
        for (int i = 0; i < 4; i++) {
            int e = tid + i * 256;
            int m = e >> 4, k = e & 15;
            As[k][m] = (k0 + k < K) ? W[(size_t)(o0 + m) * ldw + k0 + k] : 0.f;
        }
        #pragma unroll
        for (int i = 0; i < 4; i++) {
            int e = tid + i * 256;
            int k = e >> 6, n = e & 63;
            float v = 0.f;
            if (k0 + k < K) {
                v = Xb[(size_t)(k0 + k) * N + n0 + n];
                if (bnS) {
                    v = v * bnS[k0 + k] + bnF[k0 + k];
                    if (relu) v = fmaxf(v, 0.f);
                }
            }
            Bs[k][n] = v;
        }
        __syncthreads();
        #pragma unroll
        for (int kk = 0; kk < 16; kk++) {
            float a[4], bb[4];
            #pragma unroll
            for (int i = 0; i < 4; i++) a[i]  = As[kk][tm * 4 + i];
            #pragma unroll
            for (int j = 0; j < 4; j++) bb[j] = Bs[kk][tn * 4 + j];
            #pragma unroll
            for (int i = 0; i < 4; i++)
                #pragma unroll
                for (int j = 0; j < 4; j++)
                    acc[i][j] += a[i] * bb[j];
        }
        __syncthreads();
    }

    #pragma unroll
    for (int i = 0; i < 4; i++) {
        int o = o0 + tm * 4 + i;
        float bv = bias ? bias[o] : 0.f;
        size_t base = (size_t)(b * O + o) * N;
        #pragma unroll
        for (int j = 0; j < 4; j++)
            Y[base + n0 + tn * 4 + j] = acc[i][j] + bv;
    }
}

// ---------------- fp32 SGEMM 128x128, 8x8 micro, double-buffered (conv2, conv3) ----
// K multiple of 16; O multiple of 128; N multiple of 128.
__global__ void __launch_bounds__(256) gemm_f32_big(
    const float* __restrict__ X, const float* __restrict__ W,
    const float* __restrict__ bias, float* __restrict__ Y,
    int O, int K, int N, int ldw,
    const float* __restrict__ bnS, const float* __restrict__ bnF, int relu,
    float* __restrict__ Yt, int Ct, float* __restrict__ statPart)
{
    __shared__ float As[2][16][132];
    __shared__ float Bs[2][16][132];

    int b  = blockIdx.z;
    int o0 = blockIdx.y * 128;
    int n0 = blockIdx.x * 128;
    const float* Xb = X + (size_t)b * K * N;

    int tid = threadIdx.x;
    int tm  = tid >> 4;     // rows tm*8..+7
    int tn  = tid & 15;     // cols tn*8..+7

    int rowA = tid & 127;
    int kqA  = tid >> 7;    // quads kqA, kqA+2
    const float* wp = W + (size_t)(o0 + rowA) * ldw;
    int krB = tid >> 4;     // 0..15
    int nB  = (tid & 15) * 8;

    float acc[8][8] = {};
    float4 ra0, ra1, rb0, rb1;

    {
        ra0 = *(const float4*)(wp + kqA * 4);
        ra1 = *(const float4*)(wp + (kqA + 2) * 4);
        rb0 = *(const float4*)(Xb + (size_t)krB * N + n0 + nB);
        rb1 = *(const float4*)(Xb + (size_t)krB * N + n0 + nB + 4);
        As[0][kqA * 4 + 0][rowA] = ra0.x;
        As[0][kqA * 4 + 1][rowA] = ra0.y;
        As[0][kqA * 4 + 2][rowA] = ra0.z;
        As[0][kqA * 4 + 3][rowA] = ra0.w;
        As[0][(kqA + 2) * 4 + 0][rowA] = ra1.x;
        As[0][(kqA + 2) * 4 + 1][rowA] = ra1.y;
        As[0][(kqA + 2) * 4 + 2][rowA] = ra1.z;
        As[0][(kqA + 2) * 4 + 3][rowA] = ra1.w;
        float4 v0 = rb0, v1 = rb1;
        if (bnS) {
            bn4(v0, bnS[krB], bnF[krB], relu);
            bn4(v1, bnS[krB], bnF[krB], relu);
        }
        *(float4*)&Bs[0][krB][nB]     = v0;
        *(float4*)&Bs[0][krB][nB + 4] = v1;
    }
    __syncthreads();

    int nIter = K / 16;
    for (int it = 0; it < nIter; it++) {
        int s = it & 1;
        bool more = (it + 1 < nIter);
        if (more) {
            int k0 = (it + 1) * 16;
            ra0 = *(const float4*)(wp + k0 + kqA * 4);
            ra1 = *(const float4*)(wp + k0 + (kqA + 2) * 4);
            rb0 = *(const float4*)(Xb + (size_t)(k0 + krB) * N + n0 + nB);
            rb1 = *(const float4*)(Xb + (size_t)(k0 + krB) * N + n0 + nB + 4);
        }

        #pragma unroll
        for (int kk = 0; kk < 16; kk++) {
            float a[8], bb[8];
            *(float4*)&a[0]  = *(const float4*)&As[s][kk][tm * 8];
            *(float4*)&a[4]  = *(const float4*)&As[s][kk][tm * 8 + 4];
            *(float4*)&bb[0] = *(const float4*)&Bs[s][kk][tn * 8];
            *(float4*)&bb[4] = *(const float4*)&Bs[s][kk][tn * 8 + 4];
            #pragma unroll
            for (int i = 0; i < 8; i++)
                #pragma unroll
                for (int j = 0; j < 8; j++)
                    acc[i][j] += a[i] * bb[j];
        }

        if (more) {
            int d = s ^ 1;
            int k0 = (it + 1) * 16;
            As[d][kqA * 4 + 0][rowA] = ra0.x;
            As[d][kqA * 4 + 1][rowA] = ra0.y;
            As[d][kqA * 4 + 2][rowA] = ra0.z;
            As[d][kqA * 4 + 3][rowA] = ra0.w;
            As[d][(kqA + 2) * 4 + 0][rowA] = ra1.x;
            As[d][(kqA + 2) * 4 + 1][rowA] = ra1.y;
            As[d][(kqA + 2) * 4 + 2][rowA] = ra1.z;
            As[d][(kqA + 2) * 4 + 3][rowA] = ra1.w;
            float4 v0 = rb0, v1 = rb1;
            if (bnS) {
                bn4(v0, bnS[k0 + krB], bnF[k0 + krB], relu);
                bn4(v1, bnS[k0 + krB], bnF[k0 + krB], relu);
            }
            *(float4*)&Bs[d][krB][nB]     = v0;
            *(float4*)&Bs[d][krB][nB + 4] = v1;
        }
        __syncthreads();
    }

    #pragma unroll
    for (int i = 0; i < 8; i++) {
        int o = o0 + tm * 8 + i;
        float bv = bias ? bias[o] : 0.f;
        #pragma unroll
        for (int j = 0; j < 8; j++) acc[i][j] += bv;
        size_t base = (size_t)(b * O + o) * N + n0 + tn * 8;
        *(float4*)&Y[base]     = make_float4(acc[i][0], acc[i][1], acc[i][2], acc[i][3]);
        *(float4*)&Y[base + 4] = make_float4(acc[i][4], acc[i][5], acc[i][6], acc[i][7]);
    }

    if (statPart) {
        int slot = blockIdx.x + gridDim.x * b;   // 32*16 = 512 slots
        #pragma unroll
        for (int i = 0; i < 8; i++) {
            float s = 0.f, q = 0.f;
            #pragma unroll
            for (int j = 0; j < 8; j++) { s += acc[i][j]; q += acc[i][j] * acc[i][j]; }
            #pragma unroll
            for (int off = 8; off > 0; off >>= 1) {
                s += __shfl_down_sync(0xffffffff, s, off, 16);
                q += __shfl_down_sync(0xffffffff, q, off, 16);
            }
            if (tn == 0) {
                int o = o0 + tm * 8 + i;
                statPart[((size_t)o * 1024 + slot) * 2 + 0] = s;
                statPart[((size_t)o * 1024 + slot) * 2 + 1] = q;
            }
        }
    }

    if (Yt) {
        float* stage = &As[0][0][0];   // 2*16*132 = 4224 floats, holds 32n x 132
        #pragma unroll
        for (int h = 0; h < 4; h++) {
            __syncthreads();
            if ((tn >> 2) == h) {
                int nb = (tn & 3) * 8;
                #pragma unroll
                for (int j = 0; j < 8; j++)
                    #pragma unroll
                    for (int i = 0; i < 8; i++)
                        stage[(nb + j) * 132 + tm * 8 + i] = acc[i][j];
            }
            __syncthreads();
            int nn0 = tid >> 5;
            int c4  = (tid & 31) * 4;
            #pragma unroll
            for (int r = 0; r < 4; r++) {
                int nn = nn0 + r * 8;
                float4 v = *(float4*)&stage[nn * 132 + c4];
                *(float4*)&Yt[((size_t)b * NPTS + n0 + h * 32 + nn) * (size_t)Ct + o0 + c4] = v;
            }
        }
    }
}

// ---------------- tf32 GEMM, 128x128 tile, 256 thr, warp tile 32x64 ----------------
__global__ void __launch_bounds__(256) gemm_tf32(
    const float* __restrict__ X, const float* __restrict__ W,
    const float* __restrict__ bias, const float* __restrict__ biasBO,
    float* __restrict__ Y, int O, int K, int N, int ldw,
    const float* __restrict__ bnS, const float* __restrict__ bnF, int relu,
    float* __restrict__ statPart)
{
    __shared__ float As[2][16][136];
    __shared__ float Bs[2][16][136];

    int b  = blockIdx.z;
    int o0 = blockIdx.y * 128;
    int n0 = blockIdx.x * 128;
    const float* Xb = X + (size_t)b * K * N;

    int tid  = threadIdx.x;
    int lane = tid & 31;
    int warp = tid >> 5;
    int wm   = (warp & 3) * 32;
    int wn_i = warp >> 2;
    int wn   = wn_i * 64;
    int gid  = lane >> 2;
    int tig  = lane & 3;

    int rowA = tid & 127;
    int kqA  = tid >> 7;
    const float* wp = W + (size_t)(o0 + rowA) * ldw;
    int krB = tid >> 5;
    int n4  = (tid & 31) * 4;

    float acc[2][8][4] = {};
    float4 ra0, ra1, rb0, rb1;

    {
        ra0 = *(const float4*)(wp + kqA * 4);
        ra1 = *(const float4*)(wp + (kqA + 2) * 4);
        rb0 = *(const float4*)(Xb + (size_t)krB * N + n0 + n4);
        rb1 = *(const float4*)(Xb + (size_t)(krB + 8) * N + n0 + n4);
        if (bnS) {
            bn4(rb0, bnS[krB], bnF[krB], relu);
            bn4(rb1, bnS[krB + 8], bnF[krB + 8], relu);
        }
        As[0][kqA*4+0][rowA] = f2tf32f(ra0.x);
        As[0][kqA*4+1][rowA] = f2tf32f(ra0.y);
        As[0][kqA*4+2][rowA] = f2tf32f(ra0.z);
        As[0][kqA*4+3][rowA] = f2tf32f(ra0.w);
        As[0][(kqA+2)*4+0][rowA] = f2tf32f(ra1.x);
        As[0][(kqA+2)*4+1][rowA] = f2tf32f(ra1.y);
        As[0][(kqA+2)*4+2][rowA] = f2tf32f(ra1.z);
        As[0][(kqA+2)*4+3][rowA] = f2tf32f(ra1.w);
        *(float4*)&Bs[0][krB][n4] =
            make_float4(f2tf32f(rb0.x), f2tf32f(rb0.y), f2tf32f(rb0.z), f2tf32f(rb0.w));
        *(float4*)&Bs[0][krB + 8][n4] =
            make_float4(f2tf32f(rb1.x), f2tf32f(rb1.y), f2tf32f(rb1.z), f2tf32f(rb1.w));
    }
    __syncthreads();

    int nIter = K / 16;
    for (int it = 0; it < nIter; it++) {
        int s = it & 1;
        bool more = (it + 1 < nIter);
        if (more) {
            int k0 = (it + 1) * 16;
            ra0 = *(const float4*)(wp + k0 + kqA * 4);
            ra1 = *(const float4*)(wp + k0 + (kqA + 2) * 4);
            rb0 = *(const float4*)(Xb + (size_t)(k0 + krB) * N + n0 + n4);
            rb1 = *(const float4*)(Xb + (size_t)(k0 + krB + 8) * N + n0 + n4);
            if (bnS) {
                bn4(rb0, bnS[k0 + krB], bnF[k0 + krB], relu);
                bn4(rb1, bnS[k0 + krB + 8], bnF[k0 + krB + 8], relu);
            }
        }

        #pragma unroll
        for (int ks = 0; ks < 2; ks++) {
            int kk = ks * 8;
            uint32_t a[2][4], bf[8][2];
            #pragma unroll
            for (int i = 0; i < 2; i++) {
                int mr = wm + i * 16 + gid;
                a[i][0] = __float_as_uint(As[s][kk + tig    ][mr    ]);
                a[i][1] = __float_as_uint(As[s][kk + tig    ][mr + 8]);
                a[i][2] = __float_as_uint(As[s][kk + tig + 4][mr    ]);
                a[i][3] = __float_as_uint(As[s][kk + tig + 4][mr + 8]);
            }
            #pragma unroll
            for (int j = 0; j < 8; j++) {
                int nc = wn + j * 8 + gid;
                bf[j][0] = __float_as_uint(Bs[s][kk + tig    ][nc]);
                bf[j][1] = __float_as_uint(Bs[s][kk + tig + 4][nc]);
            }
            #pragma unroll
            for (int i = 0; i < 2; i++)
                #pragma unroll
                for (int j = 0; j < 8; j++)
                    mma_tf32(acc[i][j], a[i], bf[j]);
        }

        if (more) {
            int d = s ^ 1;
            As[d][kqA*4+0][rowA] = f2tf32f(ra0.x);
            As[d][kqA*4+1][rowA] = f2tf32f(ra0.y);
            As[d][kqA*4+2][rowA] = f2tf32f(ra0.z);
            As[d][kqA*4+3][rowA] = f2tf32f(ra0.w);
            As[d][(kqA+2)*4+0][rowA] = f2tf32f(ra1.x);
            As[d][(kqA+2)*4+1][rowA] = f2tf32f(ra1.y);
            As[d][(kqA+2)*4+2][rowA] = f2tf32f(ra1.z);
            As[d][(kqA+2)*4+3][rowA] = f2tf32f(ra1.w);
            *(float4*)&Bs[d][krB][n4] =
                make_float4(f2tf32f(rb0.x), f2tf32f(rb0.y), f2tf32f(rb0.z), f2tf32f(rb0.w));
            *(float4*)&Bs[d][krB + 8][n4] =
                make_float4(f2tf32f(rb1.x), f2tf32f(rb1.y), f2tf32f(rb1.z), f2tf32f(rb1.w));
        }
        __syncthreads();
    }

    float rsum[2][2], rsq[2][2];

    #pragma unroll
    for (int i = 0; i < 2; i++) {
        int r0 = o0 + wm + i * 16 + gid;
        int r1 = r0 + 8;
        float bv0 = 0.f, bv1 = 0.f;
        if (bias)   { bv0 += bias[r0]; bv1 += bias[r1]; }
        if (biasBO) { bv0 += biasBO[b * O + r0]; bv1 += biasBO[b * O + r1]; }
        size_t base0 = (size_t)(b * O + r0) * N;
        size_t base1 = (size_t)(b * O + r1) * N;
        float s0 = 0.f, s1 = 0.f, q0 = 0.f, q1 = 0.f;
        #pragma unroll
        for (int j = 0; j < 8; j++) {
            int c = n0 + wn + j * 8 + 2 * tig;
            float v00 = acc[i][j][0] + bv0, v01 = acc[i][j][1] + bv0;
            float v10 = acc[i][j][2] + bv1, v11 = acc[i][j][3] + bv1;
            *(float2*)&Y[base0 + c] = make_float2(v00, v01);
            *(float2*)&Y[base1 + c] = make_float2(v10, v11);
            s0 += v00 + v01; q0 += v00 * v00 + v01 * v01;
            s1 += v10 + v11; q1 += v10 * v10 + v11 * v11;
        }
        rsum[i][0] = s0; rsum[i][1] = s1;
        rsq[i][0]  = q0; rsq[i][1]  = q1;
    }

    if (statPart) {
        float* rs = &As[0][0][0];
        #pragma unroll
        for (int i = 0; i < 2; i++) {
            #pragma unroll
            for (int r = 0; r < 2; r++) {
                float s = rsum[i][r], q = rsq[i][r];
                #pragma unroll
                for (int off = 2; off > 0; off >>= 1) {
                    s += __shfl_down_sync(0xffffffff, s, off, 4);
                    q += __shfl_down_sync(0xffffffff, q, off, 4);
                }
                if (tig == 0) {
                    int row = wm + i * 16 + gid + r * 8;
                    rs[(row * 2 + wn_i) * 2 + 0] = s;
                    rs[(row * 2 + wn_i) * 2 + 1] = q;
                }
            }
        }
        __syncthreads();
        if (tid < 128) {
            float s = rs[(tid * 2 + 0) * 2 + 0] + rs[(tid * 2 + 1) * 2 + 0];
            float q = rs[(tid * 2 + 0) * 2 + 1] + rs[(tid * 2 + 1) * 2 + 1];
            int o = o0 + tid;
            int slot = blockIdx.x + gridDim.x * b;
            statPart[((size_t)o * 1024 + slot) * 2 + 0] = s;
            statPart[((size_t)o * 1024 + slot) * 2 + 1] = q;
        }
    }
}

// ---------------- epilogue-stats finalize -------------------------------------------
__global__ void stats_fin2(const float* __restrict__ part2, int nslots,
                           const float* __restrict__ g, const float* __restrict__ be,
                           float* __restrict__ scale, float* __restrict__ shift)
{
    int c = blockIdx.x;
    float s = 0.f, q = 0.f;
    for (int t = threadIdx.x; t < nslots; t += 256) {
        s += part2[((size_t)c * 1024 + t) * 2 + 0];
        q += part2[((size_t)c * 1024 + t) * 2 + 1];
    }
    __shared__ float sh1[256], sh2[256];
    sh1[threadIdx.x] = s; sh2[threadIdx.x] = q;
    __syncthreads();
    for (int st = 128; st > 0; st >>= 1) {
        if (threadIdx.x < st) {
            sh1[threadIdx.x] += sh1[threadIdx.x + st];
            sh2[threadIdx.x] += sh2[threadIdx.x + st];
        }
        __syncthreads();
    }
    if (threadIdx.x == 0) {
        const float inv = 1.f / (float)(B_ * NPTS);
        float m  = sh1[0] * inv;
        float v  = sh2[0] * inv - m * m;
        float sc = g[c] / sqrtf(v + 1e-5f);
        scale[c] = sc;
        shift[c] = be[c] - m * sc;
    }
}

// ---------------- conv8 fused gather GEMM (512 thr, BM=256 x BN=128, split-K 32) ---
__global__ void __launch_bounds__(512) conv8_kernel(
    const float* __restrict__ h3t, const float* __restrict__ w8tt,
    const int* __restrict__ idx, const float* __restrict__ sc3,
    const float* __restrict__ sf3, float* __restrict__ P8)
{
    __shared__ float As[2][16][264];
    __shared__ float Bs[2][16][136];
    __shared__ int   sIdx[1024];

    int col0  = blockIdx.x * 128;
    int chunk = blockIdx.y;
    int tid = threadIdx.x;
    int lane = tid & 31, warp = tid >> 5;
    int wm = (warp & 3) * 64;
    int wn = (warp >> 2) * 32;
    int gid = lane >> 2, tig = lane & 3;

    #pragma unroll
    for (int i = 0; i < 2; i++) {
        int e = tid + i * 512;
        int w8 = e >> 7, j = e & 127;
        int col = col0 + j, b = col >> 5, h = col & 31;
        sIdx[e] = idx[(((b << 8) + (chunk * 8 + w8)) << 5) + h];
    }
    __syncthreads();

    int jB = tid >> 2, cq = tid & 3;
    const float* h3b = h3t + ((size_t)((col0 + jB) >> 5) << 20);

    int kA = tid >> 5;
    int oA = (tid & 31) * 8;
    const float* abase = w8tt + (size_t)chunk * 2048 * 256;

    float acc[4][4][4] = {};
    float4 a0, a1, bv, scv, sfv;

    {
        const float* ap = abase + (size_t)kA * 256 + oA;
        a0 = *(const float4*)(ap);
        a1 = *(const float4*)(ap + 4);
        int n = sIdx[jB];
        bv  = *(const float4*)(h3b + ((size_t)n << 8) + cq * 4);
        scv = *(const float4*)(sc3 + cq * 4);
        sfv = *(const float4*)(sf3 + cq * 4);
    }
    {
        float* ar = &As[0][kA][oA];
        *(float4*)(ar)     = make_float4(f2tf32f(a0.x), f2tf32f(a0.y), f2tf32f(a0.z), f2tf32f(a0.w));
        *(float4*)(ar + 4) = make_float4(f2tf32f(a1.x), f2tf32f(a1.y), f2tf32f(a1.z), f2tf32f(a1.w));
        Bs[0][cq*4+0][jB] = f2tf32f(bv.x * scv.x + sfv.x);
        Bs[0][cq*4+1][jB] = f2tf32f(bv.y * scv.y + sfv.y);
        Bs[0][cq*4+2][jB] = f2tf32f(bv.z * scv.z + sfv.z);
        Bs[0][cq*4+3][jB] = f2tf32f(bv.w * scv.w + sfv.w);
    }
    __syncthreads();

    for (int t = 0; t < 128; t++) {
        int s = t & 1;
        bool more = (t < 127);
        if (more) {
            int t1 = t + 1;
            int w8 = t1 >> 4, c0 = (t1 & 15) * 16;
            const float* ap = abase + (size_t)(w8 * 256 + c0 + kA) * 256 + oA;
            a0 = *(const float4*)(ap);
            a1 = *(const float4*)(ap + 4);
            int n = sIdx[w8 * 128 + jB];
            bv  = *(const float4*)(h3b + ((size_t)n << 8) + c0 + cq * 4);
            scv = *(const float4*)(sc3 + c0 + cq * 4);
            sfv = *(const float4*)(sf3 + c0 + cq * 4);
        }

        #pragma unroll
        for (int ks = 0; ks < 2; ks++) {
            int kk = ks * 8;
            uint32_t a[4][4], bf[4][2];
            #pragma unroll
            for (int i = 0; i < 4; i++) {
                int mr = wm + i * 16 + gid;
                a[i][0] = __float_as_uint(As[s][kk + tig    ][mr    ]);
                a[i][1] = __float_as_uint(As[s][kk + tig    ][mr + 8]);
                a[i][2] = __float_as_uint(As[s][kk + tig + 4][mr    ]);
                a[i][3] = __float_as_uint(As[s][kk + tig + 4][mr + 8]);
            }
            #pragma unroll
            for (int j = 0; j < 4; j++) {
                int nc = wn + j * 8 + gid;
                bf[j][0] = __float_as_uint(Bs[s][kk + tig    ][nc]);
                bf[j][1] = __float_as_uint(Bs[s][kk + tig + 4][nc]);
            }
            #pragma unroll
            for (int i = 0; i < 4; i++)
                #pragma unroll
                for (int j = 0; j < 4; j++)
                    mma_tf32(acc[i][j], a[i], bf[j]);
        }

        if (more) {
            int d = s ^ 1;
            float* ar = &As[d][kA][oA];
            *(float4*)(ar)     = make_float4(f2tf32f(a0.x), f2tf32f(a0.y), f2tf32f(a0.z), f2tf32f(a0.w));
            *(float4*)(ar + 4) = make_float4(f2tf32f(a1.x), f2tf32f(a1.y), f2tf32f(a1.z), f2tf32f(a1.w));
            Bs[d][cq*4+0][jB] = f2tf32f(bv.x * scv.x + sfv.x);
            Bs[d][cq*4+1][jB] = f2tf32f(bv.y * scv.y + sfv.y);
            Bs[d][cq*4+2][jB] = f2tf32f(bv.z * scv.z + sfv.z);
            Bs[d][cq*4+3][jB] = f2tf32f(bv.w * scv.w + sfv.w);
        }
        __syncthreads();
    }

    #pragma unroll
    for (int i = 0; i < 4; i++) {
        int r0 = wm + i * 16 + gid;
        size_t base0 = ((size_t)chunk * 256 + r0) * 512 + col0;
        size_t base1 = ((size_t)chunk * 256 + r0 + 8) * 512 + col0;
        #pragma unroll
        for (int j = 0; j < 4; j++) {
            int c = wn + j * 8 + 2 * tig;
            *(float2*)&P8[base0 + c] = make_float2(acc[i][j][0], acc[i][j][1]);
            *(float2*)&P8[base1 + c] = make_float2(acc[i][j][2], acc[i][j][3]);
        }
    }
}

// ---------------- w8 transpose -----------------------------------------------------
__global__ void transpose_w8(const float* __restrict__ src, float* __restrict__ dst)
{
    __shared__ float s[32][33];
    int c = blockIdx.z, o0 = blockIdx.y * 32, w0 = blockIdx.x * 32;
    int tx = threadIdx.x, ty = threadIdx.y;
    #pragma unroll
    for (int k = 0; k < 4; k++)
        s[ty + 8 * k][tx] = src[(size_t)(o0 + ty + 8 * k) * 65536 + c * 256 + w0 + tx];
    __syncthreads();
    #pragma unroll
    for (int k = 0; k < 4; k++)
        dst[(size_t)(w0 + ty + 8 * k) * 65536 + c * 256 + o0 + tx] = s[tx][ty + 8 * k];
}

// ---------------- BN statistics (conv1 only) ----------------------------------------
__global__ void stats_kernel2(const float* __restrict__ X, float* __restrict__ part,
                              const float* __restrict__ g, const float* __restrict__ be,
                              float* __restrict__ scale, float* __restrict__ shift,
                              int* __restrict__ cnt, int C)
{
    int c = blockIdx.x, b = blockIdx.y;
    const float* p = X + ((size_t)(b * C + c)) * NPTS;
    float s = 0.f, s2 = 0.f;
    for (int t = threadIdx.x; t < NPTS / 4; t += blockDim.x) {
        float4 v = *(const float4*)&p[t * 4];
        s  += v.x + v.y + v.z + v.w;
        s2 += v.x * v.x + v.y * v.y + v.z * v.z + v.w * v.w;
    }
    __shared__ float sh1[256], sh2[256];
    sh1[threadIdx.x] = s; sh2[threadIdx.x] = s2;
    __syncthreads();
    for (int st = 128; st > 0; st >>= 1) {
        if (threadIdx.x < st) {
            sh1[threadIdx.x] += sh1[threadIdx.x + st];
            sh2[threadIdx.x] += sh2[threadIdx.x + st];
        }
        __syncthreads();
    }
    if (threadIdx.x == 0) {
        part[(c * B_ + b) * 2 + 0] = sh1[0];
        part[(c * B_ + b) * 2 + 1] = sh2[0];
        __threadfence();
        int old = atomicAdd(&cnt[c], 1);
        if (old == B_ - 1) {
            cnt[c] = 0;
            __threadfence();
            float ss = 0.f, ss2 = 0.f;
            #pragma unroll
            for (int bb = 0; bb < B_; bb++) {
                ss  += part[(c * B_ + bb) * 2 + 0];
                ss2 += part[(c * B_ + bb) * 2 + 1];
            }
            const float inv = 1.f / (float)(B_ * NPTS);
            float m  = ss * inv;
            float v  = ss2 * inv - m * m;
            float sc = g[c] / sqrtf(v + 1e-5f);
            scale[c] = sc;
            shift[c] = be[c] - m * sc;
        }
    }
}

// ---------------- exact top-32 per (b,c) row — incremental ---------------------------
__global__ void topk_kernel(const float* __restrict__ X, int* __restrict__ idx_out)
{
    int bc = blockIdx.x;
    const float* row = X + (size_t)bc * NPTS;
    int tid  = threadIdx.x;
    int lane = tid & 31;
    int warp = tid >> 5;

    float v[16];
    #pragma unroll
    for (int j = 0; j < 16; j++) v[j] = row[j * 256 + tid];

    float lv = -FLT_MAX; int li = 0x7fffffff;
    #pragma unroll
    for (int j = 0; j < 16; j++) {
        int n = j * 256 + tid;
        if (v[j] > lv || (v[j] == lv && n < li)) { lv = v[j]; li = n; }
    }

    __shared__ float swv[8];
    __shared__ int   swi[8];
    __shared__ int   sbi;

    {
        float tv = lv; int ti = li;
        #pragma unroll
        for (int off = 16; off > 0; off >>= 1) {
            float ov = __shfl_down_sync(0xffffffff, tv, off);
            int   oi = __shfl_down_sync(0xffffffff, ti, off);
            if (ov > tv || (ov == tv && oi < ti)) { tv = ov; ti = oi; }
        }
        if (lane == 0) { swv[warp] = tv; swi[warp] = ti; }
    }
    __syncthreads();

    for (int iter = 0; iter < 32; iter++) {
        if (tid == 0) {
            float gv = swv[0]; int gi = swi[0];
            #pragma unroll
            for (int w = 1; w < 8; w++)
                if (swv[w] > gv || (swv[w] == gv && swi[w] < gi)) { gv = swv[w]; gi = swi[w]; }
            sbi = gi;
            idx_out[bc * 32 + iter] = gi;
        }
        __syncthreads();
        if (iter == 31) break;
        int gi = sbi;
        int ow = (gi & 255) >> 5;
        if ((gi & 255) == tid) {
            v[gi >> 8] = -FLT_MAX;
            lv = -FLT_MAX; li = 0x7fffffff;
            #pragma unroll
            for (int j = 0; j < 16; j++) {
                int n = j * 256 + tid;
                if (v[j] > lv || (v[j] == lv && n < li)) { lv = v[j]; li = n; }
            }
        }
        if (warp == ow) {
            float tv = lv; int ti = li;
            #pragma unroll
            for (int off = 16; off > 0; off >>= 1) {
                float ov = __shfl_down_sync(0xffffffff, tv, off);
                int   oi = __shfl_down_sync(0xffffffff, ti, off);
                if (ov > tv || (ov == tv && oi < ti)) { tv = ov; ti = oi; }
            }
            if (lane == 0) { swv[ow] = tv; swi[ow] = ti; }
        }
        __syncthreads();
    }
}

// ---------------- conv8 split-K reduce (32 chunks) ----------------------------------
__global__ void reduce8_kernel(const float* __restrict__ P, const float* __restrict__ b8,
                               float* __restrict__ y8)
{
    int i = blockIdx.x * blockDim.x + threadIdx.x;
    float s = b8[i >> 9];
    #pragma unroll
    for (int ch = 0; ch < 32; ch++) s += P[(size_t)ch * 131072 + i];
    y8[i] = s;
}

// ---------------- conv9 ------------------------------------------------------------
__global__ void conv9_kernel(const float* __restrict__ y8, const float* __restrict__ w9,
                             const float* __restrict__ b9, float* __restrict__ y9)
{
    int b = blockIdx.x >> 8;
    int o = blockIdx.x & 255;
    int c = threadIdx.x;
    float s = 0.f;
    const float* yb = y8 + (size_t)c * 512 + b * 32;
    const float* wr = w9 + ((size_t)o * 256 + c) * 32;
    #pragma unroll
    for (int h = 0; h < 32; h++) s += yb[h] * wr[h];
    __shared__ float sh[256];
    sh[c] = s; __syncthreads();
    for (int st = 128; st > 0; st >>= 1) {
        if (c < st) sh[c] += sh[c + st];
        __syncthreads();
    }
    if (c == 0) y9[b * 256 + o] = sh[0] + b9[o];
}

// ---------------- glob contribution to conv4 ---------------------------------------
__global__ void gcon_kernel(const float* __restrict__ w4, const float* __restrict__ y9,
                            float* __restrict__ gcon)
{
    int i = blockIdx.x * blockDim.x + threadIdx.x;
    int b = i >> 9, o = i & 511;
    float s = 0.f;
    for (int c = 0; c < 256; c++) s += w4[o * 320 + c] * y9[b * 256 + c];
    gcon[i] = s;
}

// ---------------- conv7 + bn6 + relu + tanh ----------------------------------------
__global__ void conv7_kernel(const float* __restrict__ h6, const float* __restrict__ sc,
                             const float* __restrict__ sf, const float* __restrict__ w7,
                             const float* __restrict__ b7, float* __restrict__ out)
{
    int i = blockIdx.x * blockDim.x + threadIdx.x;
    int b = i >> 12, n = i & (NPTS - 1);
    float s0 = b7[0], s1 = b7[1], s2 = b7[2];
    const float* hb = h6 + (((size_t)b * 128) << 12) + n;
    for (int c = 0; c < 128; c++) {
        float v = fmaxf(hb[(size_t)c * NPTS] * sc[c] + sf[c], 0.f);
        s0 += w7[c] * v;
        s1 += w7[128 + c] * v;
        s2 += w7[256 + c] * v;
    }
    out[((size_t)(b * 3 + 0)) * NPTS + n] = tanhf(s0);
    out[((size_t)(b * 3 + 1)) * NPTS + n] = tanhf(s1);
    out[((size_t)(b * 3 + 2)) * NPTS + n] = tanhf(s2);
}

// ===================================================================================
extern "C" void kernel_launch(void* const* d_in, const int* in_sizes, int n_in,
                              void* d_out, int out_size)
{
    const float* x   = (const float*)d_in[0];
    const float* w1  = (const float*)d_in[1];
    const float* b1  = (const float*)d_in[2];
    const float* g1  = (const float*)d_in[3];
    const float* be1 = (const float*)d_in[4];
    const float* w2  = (const float*)d_in[5];
    const float* b2  = (const float*)d_in[6];
    const float* g2  = (const float*)d_in[7];
    const float* be2 = (const float*)d_in[8];
    const float* w3  = (const float*)d_in[9];
    const float* b3  = (const float*)d_in[10];
    const float* g3  = (const float*)d_in[11];
    const float* be3 = (const float*)d_in[12];
    const float* w4  = (const float*)d_in[13];
    const float* b4  = (const float*)d_in[14];
    const float* g4  = (const float*)d_in[15];
    const float* be4 = (const float*)d_in[16];
    const float* w5  = (const float*)d_in[17];
    const float* b5  = (const float*)d_in[18];
    const float* g5  = (const float*)d_in[19];
    const float* be5 = (const float*)d_in[20];
    const float* w6  = (const float*)d_in[21];
    const float* b6  = (const float*)d_in[22];
    const float* g6  = (const float*)d_in[23];
    const float* be6 = (const float*)d_in[24];
    const float* w7  = (const float*)d_in[25];
    const float* b7  = (const float*)d_in[26];
    const float* w8  = (const float*)d_in[27];
    const float* b8  = (const float*)d_in[28];
    const float* w9  = (const float*)d_in[29];
    const float* b9  = (const float*)d_in[30];
    float* out = (float*)d_out;

    float *h1, *h2, *h3, *h3t, *h4, *h5, *h6, *w8t, *P8, *y8, *y9, *gcon, *scale, *shift;
    float *part, *part2;
    int *idxp, *cnt;
    cudaGetSymbolAddress((void**)&h1,    g_h1);
    cudaGetSymbolAddress((void**)&h2,    g_h2);
    cudaGetSymbolAddress((void**)&h3,    g_h3);
    cudaGetSymbolAddress((void**)&h3t,   g_h3t);
    cudaGetSymbolAddress((void**)&h4,    g_h4);
    cudaGetSymbolAddress((void**)&h5,    g_h5);
    cudaGetSymbolAddress((void**)&h6,    g_h6);
    cudaGetSymbolAddress((void**)&w8t,   g_w8t);
    cudaGetSymbolAddress((void**)&P8,    g_P8);
    cudaGetSymbolAddress((void**)&y8,    g_y8);
    cudaGetSymbolAddress((void**)&y9,    g_y9);
    cudaGetSymbolAddress((void**)&gcon,  g_gcon);
    cudaGetSymbolAddress((void**)&idxp,  g_idx);
    cudaGetSymbolAddress((void**)&scale, g_scale);
    cudaGetSymbolAddress((void**)&shift, g_shift);
    cudaGetSymbolAddress((void**)&part,  g_part);
    cudaGetSymbolAddress((void**)&part2, g_part2);
    cudaGetSymbolAddress((void**)&cnt,   g_cnt);

    float* sc1 = scale + 0 * 512; float* sf1 = shift + 0 * 512;
    float* sc2 = scale + 1 * 512; float* sf2 = shift + 1 * 512;
    float* sc3 = scale + 2 * 512; float* sf3 = shift + 2 * 512;
    float* sc4 = scale + 3 * 512; float* sf4 = shift + 3 * 512;
    float* sc5 = scale + 4 * 512; float* sf5 = shift + 4 * 512;
    float* sc6 = scale + 5 * 512; float* sf6 = shift + 5 * 512;

    // conv1 (4->64), raw out (exact fp32, tiny K)
    gemm_f32<<<dim3(64, 1, B_), 256>>>(x, w1, b1, h1, 64, 4, NPTS, 4, nullptr, nullptr, 0);
    stats_kernel2<<<dim3(64, B_), 256>>>(h1, part, g1, be1, sc1, sf1, cnt, 64);

    // conv2 (64->128), bn1+relu fused; 128x128 tile; stats fused (512 slots)
    gemm_f32_big<<<dim3(32, 1, B_), 256>>>(h1, w2, b2, h2, 128, 64, NPTS, 64, sc1, sf1, 1,
                                           nullptr, 0, part2);
    stats_fin2<<<128, 256>>>(part2, 512, g2, be2, sc2, sf2);

    // conv3 (128->256), bn2+relu fused, dual-writes h3 and h3t; stats fused
    gemm_f32_big<<<dim3(32, 2, B_), 256>>>(h2, w3, b3, h3, 256, 128, NPTS, 128, sc2, sf2, 1,
                                           h3t, 256, part2);

    // top-32 on raw h3 (order preserved under positive BN scale)
    topk_kernel<<<B_ * 256, 256>>>(h3, idxp);

    stats_fin2<<<256, 256>>>(part2, 512, g3, be3, sc3, sf3);
    transpose_w8<<<dim3(8, 8, 256), dim3(32, 8)>>>(w8, w8t);

    // conv8 fused gather GEMM (bn3 in gather), split-K 32, BM256xBN128, 128 CTAs
    conv8_kernel<<<dim3(4, 32), 512>>>(h3t, w8t, idxp, sc3, sf3, P8);
    reduce8_kernel<<<(256 * 512) / 256, 256>>>(P8, b8, y8);

    conv9_kernel<<<B_ * 256, 256>>>(y8, w9, b9, y9);
    gcon_kernel<<<(B_ * 512) / 256, 256>>>(w4, y9, gcon);

    // conv4 (64->512) tf32 128x128, bn1+relu fused, + gcon; stats fused
    gemm_tf32<<<dim3(32, 4, B_), 256>>>(h1, w4 + 256, b4, gcon, h4, 512, 64, NPTS, 320,
                                        sc1, sf1, 1, part2);
    stats_fin2<<<512, 256>>>(part2, 32 * B_, g4, be4, sc4, sf4);

    // conv5 (512->256) tf32 128x128, bn4+relu fused; stats fused
    gemm_tf32<<<dim3(32, 2, B_), 256>>>(h4, w5, b5, nullptr, h5, 256, 512, NPTS, 512,
                                        sc4, sf4, 1, part2);
    stats_fin2<<<256, 256>>>(part2, 32 * B_, g5, be5, sc5, sf5);

    // conv6 (256->128) tf32 128x128, bn5+relu fused; stats fused
    gemm_tf32<<<dim3(32, 1, B_), 256>>>(h5, w6, b6, nullptr, h6, 128, 256, NPTS, 256,
                                        sc5, sf5, 1, part2);
    stats_fin2<<<128, 256>>>(part2, 32 * B_, g6, be6, sc6, sf6);

    // conv7 (128->3) + bn6 + relu + tanh
    conv7_kernel<<<(B_ * NPTS) / 256, 256>>>(h6, sc6, sf6, w7, b7, out);
}

// round 16
// speedup vs baseline: 1.0324x; 1.0324x over previous
#include <cuda_runtime.h>
#include <math.h>
#include <float.h>
#include <stdint.h>

#define B_    16
#define NPTS  4096

// ---------------- scratch (static device globals) ---------------------------------
__device__ float g_h1[(size_t)B_ * 64  * NPTS];
__device__ float g_h2[(size_t)B_ * 128 * NPTS];
__device__ float g_h3[(size_t)B_ * 256 * NPTS];
__device__ float g_h3t[(size_t)B_ * NPTS * 256];   // [b][n][c]
__device__ float g_h4[(size_t)B_ * 512 * NPTS];
__device__ float g_h5[(size_t)B_ * 256 * NPTS];
__device__ float g_h6[(size_t)B_ * 128 * NPTS];
__device__ float g_w8t[(size_t)256 * 256 * 256];   // [w][c][o]
__device__ float g_P8[(size_t)32 * 256 * 512];     // split-K partials for conv8 (32 chunks)
__device__ float g_y8[256 * 512];                  // conv8 out, [o][b*32+h]
__device__ float g_y9[B_ * 512];
__device__ float g_gcon[B_ * 512];
__device__ int   g_idx[B_ * 256 * 32];
__device__ float g_scale[6 * 512];
__device__ float g_shift[6 * 512];
__device__ float g_part2[(size_t)512 * 1024 * 2];  // epilogue stats partials [c][slot][2]

__device__ __forceinline__ float f2tf32f(float f) {
    uint32_t u;
    asm("cvt.rna.tf32.f32 %0, %1;" : "=r"(u) : "f"(f));
    return __uint_as_float(u);
}

__device__ __forceinline__ void mma_tf32(float* d, const uint32_t* a, const uint32_t* b) {
    asm volatile(
        "mma.sync.aligned.m16n8k8.row.col.f32.tf32.tf32.f32 "
        "{%0,%1,%2,%3}, {%4,%5,%6,%7}, {%8,%9}, {%0,%1,%2,%3};"
        : "+f"(d[0]), "+f"(d[1]), "+f"(d[2]), "+f"(d[3])
        : "r"(a[0]), "r"(a[1]), "r"(a[2]), "r"(a[3]), "r"(b[0]), "r"(b[1]));
}

__device__ __forceinline__ void bn4(float4& v, float sc, float sf, int relu) {
    v.x = v.x * sc + sf; v.y = v.y * sc + sf;
    v.z = v.z * sc + sf; v.w = v.w * sc + sf;
    if (relu) {
        v.x = fmaxf(v.x, 0.f); v.y = fmaxf(v.y, 0.f);
        v.z = fmaxf(v.z, 0.f); v.w = fmaxf(v.w, 0.f);
    }
}

// ---------------- fp32 SGEMM 64x64 (conv1 only: K=4) + fused stats ------------------
__global__ void gemm_f32(const float* __restrict__ X, const float* __restrict__ W,
                         const float* __restrict__ bias, float* __restrict__ Y,
                         int O, int K, int N, int ldw,
                         const float* __restrict__ bnS, const float* __restrict__ bnF,
                         int relu, float* __restrict__ statPart)
{
    __shared__ float As[16][66];
    __shared__ float Bs[16][64];

    int b  = blockIdx.z;
    int o0 = blockIdx.y * 64;
    int n0 = blockIdx.x * 64;
    const float* Xb = X + (size_t)b * K * N;

    int tid = threadIdx.x;
    int tm  = tid >> 4;
    int tn  = tid & 15;

    float acc[4][4] = {};

    for (int k0 = 0; k0 < K; k0 += 16) {
        #pragma unroll
        for (int i = 0; i < 4; i++) {
            int e = tid + i * 256;
            int m = e >> 4, k = e & 15;
            As[k][m] = (k0 + k < K) ? W[(size_t)(o0 + m) * ldw + k0 + k] : 0.f;
        }
        #pragma unroll
        for (int i = 0; i < 4; i++) {
            int e = tid + i * 256;
            int k = e >> 6, n = e & 63;
            float v = 0.f;
            if (k0 + k < K) {
                v = Xb[(size_t)(k0 + k) * N + n0 + n];
                if (bnS) {
                    v = v * bnS[k0 + k] + bnF[k0 + k];
                    if (relu) v = fmaxf(v, 0.f);
                }
            }
            Bs[k][n] = v;
        }
        __syncthreads();
        #pragma unroll
        for (int kk = 0; kk < 16; kk++) {
            float a[4], bb[4];
            #pragma unroll
            for (int i = 0; i < 4; i++) a[i]  = As[kk][tm * 4 + i];
            #pragma unroll
            for (int j = 0; j < 4; j++) bb[j] = Bs[kk][tn * 4 + j];
            #pragma unroll
            for (int i = 0; i < 4; i++)
                #pragma unroll
                for (int j = 0; j < 4; j++)
                    acc[i][j] += a[i] * bb[j];
        }
        __syncthreads();
    }

    #pragma unroll
    for (int i = 0; i < 4; i++) {
        int o = o0 + tm * 4 + i;
        float bv = bias ? bias[o] : 0.f;
        #pragma unroll
        for (int j = 0; j < 4; j++) acc[i][j] += bv;
        size_t base = (size_t)(b * O + o) * N;
        *(float4*)&Y[base + n0 + tn * 4] =
            make_float4(acc[i][0], acc[i][1], acc[i][2], acc[i][3]);
    }

    if (statPart) {
        int slot = blockIdx.x + gridDim.x * b;   // 64*16 = 1024 slots
        #pragma unroll
        for (int i = 0; i < 4; i++) {
            float s = acc[i][0] + acc[i][1] + acc[i][2] + acc[i][3];
            float q = acc[i][0] * acc[i][0] + acc[i][1] * acc[i][1]
                    + acc[i][2] * acc[i][2] + acc[i][3] * acc[i][3];
            #pragma unroll
            for (int off = 8; off > 0; off >>= 1) {
                s += __shfl_down_sync(0xffffffff, s, off, 16);
                q += __shfl_down_sync(0xffffffff, q, off, 16);
            }
            if (tn == 0) {
                int o = o0 + tm * 4 + i;
                statPart[((size_t)o * 1024 + slot) * 2 + 0] = s;
                statPart[((size_t)o * 1024 + slot) * 2 + 1] = q;
            }
        }
    }
}

// ---------------- fp32 SGEMM 128x64, 8x4 micro, double-buffered (conv2, conv3) -----
__global__ void __launch_bounds__(256) gemm_f32_big(
    const float* __restrict__ X, const float* __restrict__ W,
    const float* __restrict__ bias, float* __restrict__ Y,
    int O, int K, int N, int ldw,
    const float* __restrict__ bnS, const float* __restrict__ bnF, int relu,
    float* __restrict__ Yt, int Ct, float* __restrict__ statPart)
{
    __shared__ float As[2][16][132];
    __shared__ float Bs[2][16][68];

    int b  = blockIdx.z;
    int o0 = blockIdx.y * 128;
    int n0 = blockIdx.x * 64;
    const float* Xb = X + (size_t)b * K * N;

    int tid = threadIdx.x;
    int tm  = tid >> 4;
    int tn  = tid & 15;

    int rowA = tid & 127;
    int kqA  = tid >> 7;
    const float* wp = W + (size_t)(o0 + rowA) * ldw;
    int krB = tid >> 4;
    int n4  = (tid & 15) * 4;

    float acc[8][4] = {};
    float4 ra0, ra1, rb;

    {
        ra0 = *(const float4*)(wp + kqA * 4);
        ra1 = *(const float4*)(wp + (kqA + 2) * 4);
        rb  = *(const float4*)(Xb + (size_t)krB * N + n0 + n4);
        As[0][kqA * 4 + 0][rowA] = ra0.x;
        As[0][kqA * 4 + 1][rowA] = ra0.y;
        As[0][kqA * 4 + 2][rowA] = ra0.z;
        As[0][kqA * 4 + 3][rowA] = ra0.w;
        As[0][(kqA + 2) * 4 + 0][rowA] = ra1.x;
        As[0][(kqA + 2) * 4 + 1][rowA] = ra1.y;
        As[0][(kqA + 2) * 4 + 2][rowA] = ra1.z;
        As[0][(kqA + 2) * 4 + 3][rowA] = ra1.w;
        float4 v = rb;
        if (bnS) bn4(v, bnS[krB], bnF[krB], relu);
        *(float4*)&Bs[0][krB][n4] = v;
    }
    __syncthreads();

    int nIter = K / 16;
    for (int it = 0; it < nIter; it++) {
        int s = it & 1;
        bool more = (it + 1 < nIter);
        if (more) {
            int k0 = (it + 1) * 16;
            ra0 = *(const float4*)(wp + k0 + kqA * 4);
            ra1 = *(const float4*)(wp + k0 + (kqA + 2) * 4);
            rb  = *(const float4*)(Xb + (size_t)(k0 + krB) * N + n0 + n4);
        }

        #pragma unroll
        for (int kk = 0; kk < 16; kk++) {
            float a[8], bb[4];
            *(float4*)&a[0] = *(const float4*)&As[s][kk][tm * 8];
            *(float4*)&a[4] = *(const float4*)&As[s][kk][tm * 8 + 4];
            *(float4*)&bb[0] = *(const float4*)&Bs[s][kk][tn * 4];
            #pragma unroll
            for (int i = 0; i < 8; i++)
                #pragma unroll
                for (int j = 0; j < 4; j++)
                    acc[i][j] += a[i] * bb[j];
        }

        if (more) {
            int d = s ^ 1;
            As[d][kqA * 4 + 0][rowA] = ra0.x;
            As[d][kqA * 4 + 1][rowA] = ra0.y;
            As[d][kqA * 4 + 2][rowA] = ra0.z;
            As[d][kqA * 4 + 3][rowA] = ra0.w;
            As[d][(kqA + 2) * 4 + 0][rowA] = ra1.x;
            As[d][(kqA + 2) * 4 + 1][rowA] = ra1.y;
            As[d][(kqA + 2) * 4 + 2][rowA] = ra1.z;
            As[d][(kqA + 2) * 4 + 3][rowA] = ra1.w;
            float4 v = rb;
            if (bnS) bn4(v, bnS[(it + 1) * 16 + krB], bnF[(it + 1) * 16 + krB], relu);
            *(float4*)&Bs[d][krB][n4] = v;
        }
        __syncthreads();
    }

    #pragma unroll
    for (int i = 0; i < 8; i++) {
        int o = o0 + tm * 8 + i;
        float bv = bias ? bias[o] : 0.f;
        #pragma unroll
        for (int j = 0; j < 4; j++) acc[i][j] += bv;
        *(float4*)&Y[(size_t)(b * O + o) * N + n0 + tn * 4] =
            make_float4(acc[i][0], acc[i][1], acc[i][2], acc[i][3]);
    }

    if (statPart) {
        int slot = blockIdx.x + gridDim.x * b;
        #pragma unroll
        for (int i = 0; i < 8; i++) {
            float s = acc[i][0] + acc[i][1] + acc[i][2] + acc[i][3];
            float q = acc[i][0] * acc[i][0] + acc[i][1] * acc[i][1]
                    + acc[i][2] * acc[i][2] + acc[i][3] * acc[i][3];
            #pragma unroll
            for (int off = 8; off > 0; off >>= 1) {
                s += __shfl_down_sync(0xffffffff, s, off, 16);
                q += __shfl_down_sync(0xffffffff, q, off, 16);
            }
            if (tn == 0) {
                int o = o0 + tm * 8 + i;
                statPart[((size_t)o * 1024 + slot) * 2 + 0] = s;
                statPart[((size_t)o * 1024 + slot) * 2 + 1] = q;
            }
        }
    }

    if (Yt) {
        float* stage = &As[0][0][0];
        #pragma unroll
        for (int h = 0; h < 2; h++) {
            __syncthreads();
            if ((tn >> 3) == h) {
                int nb = (tn & 7) * 4;
                #pragma unroll
                for (int j = 0; j < 4; j++)
                    #pragma unroll
                    for (int i = 0; i < 8; i++)
                        stage[(nb + j) * 132 + tm * 8 + i] = acc[i][j];
            }
            __syncthreads();
            int nn0 = tid >> 5;
            int c4  = (tid & 31) * 4;
            #pragma unroll
            for (int r = 0; r < 4; r++) {
                int nn = nn0 + r * 8;
                float4 v = *(float4*)&stage[nn * 132 + c4];
                *(float4*)&Yt[((size_t)b * NPTS + n0 + h * 32 + nn) * (size_t)Ct + o0 + c4] = v;
            }
        }
    }
}

// ---------------- tf32 GEMM, 128x128 tile, 256 thr, warp tile 32x64 ----------------
__global__ void __launch_bounds__(256) gemm_tf32(
    const float* __restrict__ X, const float* __restrict__ W,
    const float* __restrict__ bias, const float* __restrict__ biasBO,
    float* __restrict__ Y, int O, int K, int N, int ldw,
    const float* __restrict__ bnS, const float* __restrict__ bnF, int relu,
    float* __restrict__ statPart)
{
    __shared__ float As[2][16][136];
    __shared__ float Bs[2][16][136];

    int b  = blockIdx.z;
    int o0 = blockIdx.y * 128;
    int n0 = blockIdx.x * 128;
    const float* Xb = X + (size_t)b * K * N;

    int tid  = threadIdx.x;
    int lane = tid & 31;
    int warp = tid >> 5;
    int wm   = (warp & 3) * 32;
    int wn_i = warp >> 2;
    int wn   = wn_i * 64;
    int gid  = lane >> 2;
    int tig  = lane & 3;

    int rowA = tid & 127;
    int kqA  = tid >> 7;
    const float* wp = W + (size_t)(o0 + rowA) * ldw;
    int krB = tid >> 5;
    int n4  = (tid & 31) * 4;

    float acc[2][8][4] = {};
    float4 ra0, ra1, rb0, rb1;

    {
        ra0 = *(const float4*)(wp + kqA * 4);
        ra1 = *(const float4*)(wp + (kqA + 2) * 4);
        rb0 = *(const float4*)(Xb + (size_t)krB * N + n0 + n4);
        rb1 = *(const float4*)(Xb + (size_t)(krB + 8) * N + n0 + n4);
        if (bnS) {
            bn4(rb0, bnS[krB], bnF[krB], relu);
            bn4(rb1, bnS[krB + 8], bnF[krB + 8], relu);
        }
        As[0][kqA*4+0][rowA] = f2tf32f(ra0.x);
        As[0][kqA*4+1][rowA] = f2tf32f(ra0.y);
        As[0][kqA*4+2][rowA] = f2tf32f(ra0.z);
        As[0][kqA*4+3][rowA] = f2tf32f(ra0.w);
        As[0][(kqA+2)*4+0][rowA] = f2tf32f(ra1.x);
        As[0][(kqA+2)*4+1][rowA] = f2tf32f(ra1.y);
        As[0][(kqA+2)*4+2][rowA] = f2tf32f(ra1.z);
        As[0][(kqA+2)*4+3][rowA] = f2tf32f(ra1.w);
        *(float4*)&Bs[0][krB][n4] =
            make_float4(f2tf32f(rb0.x), f2tf32f(rb0.y), f2tf32f(rb0.z), f2tf32f(rb0.w));
        *(float4*)&Bs[0][krB + 8][n4] =
            make_float4(f2tf32f(rb1.x), f2tf32f(rb1.y), f2tf32f(rb1.z), f2tf32f(rb1.w));
    }
    __syncthreads();

    int nIter = K / 16;
    for (int it = 0; it < nIter; it++) {
        int s = it & 1;
        bool more = (it + 1 < nIter);
        if (more) {
            int k0 = (it + 1) * 16;
            ra0 = *(const float4*)(wp + k0 + kqA * 4);
            ra1 = *(const float4*)(wp + k0 + (kqA + 2) * 4);
            rb0 = *(const float4*)(Xb + (size_t)(k0 + krB) * N + n0 + n4);
            rb1 = *(const float4*)(Xb + (size_t)(k0 + krB + 8) * N + n0 + n4);
            if (bnS) {
                bn4(rb0, bnS[k0 + krB], bnF[k0 + krB], relu);
                bn4(rb1, bnS[k0 + krB + 8], bnF[k0 + krB + 8], relu);
            }
        }

        #pragma unroll
        for (int ks = 0; ks < 2; ks++) {
            int kk = ks * 8;
            uint32_t a[2][4], bf[8][2];
            #pragma unroll
            for (int i = 0; i < 2; i++) {
                int mr = wm + i * 16 + gid;
                a[i][0] = __float_as_uint(As[s][kk + tig    ][mr    ]);
                a[i][1] = __float_as_uint(As[s][kk + tig    ][mr + 8]);
                a[i][2] = __float_as_uint(As[s][kk + tig + 4][mr    ]);
                a[i][3] = __float_as_uint(As[s][kk + tig + 4][mr + 8]);
            }
            #pragma unroll
            for (int j = 0; j < 8; j++) {
                int nc = wn + j * 8 + gid;
                bf[j][0] = __float_as_uint(Bs[s][kk + tig    ][nc]);
                bf[j][1] = __float_as_uint(Bs[s][kk + tig + 4][nc]);
            }
            #pragma unroll
            for (int i = 0; i < 2; i++)
                #pragma unroll
                for (int j = 0; j < 8; j++)
                    mma_tf32(acc[i][j], a[i], bf[j]);
        }

        if (more) {
            int d = s ^ 1;
            As[d][kqA*4+0][rowA] = f2tf32f(ra0.x);
            As[d][kqA*4+1][rowA] = f2tf32f(ra0.y);
            As[d][kqA*4+2][rowA] = f2tf32f(ra0.z);
            As[d][kqA*4+3][rowA] = f2tf32f(ra0.w);
            As[d][(kqA+2)*4+0][rowA] = f2tf32f(ra1.x);
            As[d][(kqA+2)*4+1][rowA] = f2tf32f(ra1.y);
            As[d][(kqA+2)*4+2][rowA] = f2tf32f(ra1.z);
            As[d][(kqA+2)*4+3][rowA] = f2tf32f(ra1.w);
            *(float4*)&Bs[d][krB][n4] =
                make_float4(f2tf32f(rb0.x), f2tf32f(rb0.y), f2tf32f(rb0.z), f2tf32f(rb0.w));
            *(float4*)&Bs[d][krB + 8][n4] =
                make_float4(f2tf32f(rb1.x), f2tf32f(rb1.y), f2tf32f(rb1.z), f2tf32f(rb1.w));
        }
        __syncthreads();
    }

    float rsum[2][2], rsq[2][2];

    #pragma unroll
    for (int i = 0; i < 2; i++) {
        int r0 = o0 + wm + i * 16 + gid;
        int r1 = r0 + 8;
        float bv0 = 0.f, bv1 = 0.f;
        if (bias)   { bv0 += bias[r0]; bv1 += bias[r1]; }
        if (biasBO) { bv0 += biasBO[b * O + r0]; bv1 += biasBO[b * O + r1]; }
        size_t base0 = (size_t)(b * O + r0) * N;
        size_t base1 = (size_t)(b * O + r1) * N;
        float s0 = 0.f, s1 = 0.f, q0 = 0.f, q1 = 0.f;
        #pragma unroll
        for (int j = 0; j < 8; j++) {
            int c = n0 + wn + j * 8 + 2 * tig;
            float v00 = acc[i][j][0] + bv0, v01 = acc[i][j][1] + bv0;
            float v10 = acc[i][j][2] + bv1, v11 = acc[i][j][3] + bv1;
            *(float2*)&Y[base0 + c] = make_float2(v00, v01);
            *(float2*)&Y[base1 + c] = make_float2(v10, v11);
            s0 += v00 + v01; q0 += v00 * v00 + v01 * v01;
            s1 += v10 + v11; q1 += v10 * v10 + v11 * v11;
        }
        rsum[i][0] = s0; rsum[i][1] = s1;
        rsq[i][0]  = q0; rsq[i][1]  = q1;
    }

    if (statPart) {
        float* rs = &As[0][0][0];
        #pragma unroll
        for (int i = 0; i < 2; i++) {
            #pragma unroll
            for (int r = 0; r < 2; r++) {
                float s = rsum[i][r], q = rsq[i][r];
                #pragma unroll
                for (int off = 2; off > 0; off >>= 1) {
                    s += __shfl_down_sync(0xffffffff, s, off, 4);
                    q += __shfl_down_sync(0xffffffff, q, off, 4);
                }
                if (tig == 0) {
                    int row = wm + i * 16 + gid + r * 8;
                    rs[(row * 2 + wn_i) * 2 + 0] = s;
                    rs[(row * 2 + wn_i) * 2 + 1] = q;
                }
            }
        }
        __syncthreads();
        if (tid < 128) {
            float s = rs[(tid * 2 + 0) * 2 + 0] + rs[(tid * 2 + 1) * 2 + 0];
            float q = rs[(tid * 2 + 0) * 2 + 1] + rs[(tid * 2 + 1) * 2 + 1];
            int o = o0 + tid;
            int slot = blockIdx.x + gridDim.x * b;
            statPart[((size_t)o * 1024 + slot) * 2 + 0] = s;
            statPart[((size_t)o * 1024 + slot) * 2 + 1] = q;
        }
    }
}

// ---------------- epilogue-stats finalize -------------------------------------------
__global__ void stats_fin2(const float* __restrict__ part2, int nslots,
                           const float* __restrict__ g, const float* __restrict__ be,
                           float* __restrict__ scale, float* __restrict__ shift)
{
    int c = blockIdx.x;
    float s = 0.f, q = 0.f;
    for (int t = threadIdx.x; t < nslots; t += 256) {
        s += part2[((size_t)c * 1024 + t) * 2 + 0];
        q += part2[((size_t)c * 1024 + t) * 2 + 1];
    }
    __shared__ float sh1[256], sh2[256];
    sh1[threadIdx.x] = s; sh2[threadIdx.x] = q;
    __syncthreads();
    for (int st = 128; st > 0; st >>= 1) {
        if (threadIdx.x < st) {
            sh1[threadIdx.x] += sh1[threadIdx.x + st];
            sh2[threadIdx.x] += sh2[threadIdx.x + st];
        }
        __syncthreads();
    }
    if (threadIdx.x == 0) {
        const float inv = 1.f / (float)(B_ * NPTS);
        float m  = sh1[0] * inv;
        float v  = sh2[0] * inv - m * m;
        float sc = g[c] / sqrtf(v + 1e-5f);
        scale[c] = sc;
        shift[c] = be[c] - m * sc;
    }
}

// ---------------- conv8 fused gather GEMM (512 thr, BM=256 x BN=128, split-K 32) ---
__global__ void __launch_bounds__(512) conv8_kernel(
    const float* __restrict__ h3t, const float* __restrict__ w8tt,
    const int* __restrict__ idx, const float* __restrict__ sc3,
    const float* __restrict__ sf3, float* __restrict__ P8)
{
    __shared__ float As[2][16][264];
    __shared__ float Bs[2][16][136];
    __shared__ int   sIdx[1024];

    int col0  = blockIdx.x * 128;
    int chunk = blockIdx.y;
    int tid = threadIdx.x;
    int lane = tid & 31, warp = tid >> 5;
    int wm = (warp & 3) * 64;
    int wn = (warp >> 2) * 32;
    int gid = lane >> 2, tig = lane & 3;

    #pragma unroll
    for (int i = 0; i < 2; i++) {
        int e = tid + i * 512;
        int w8 = e >> 7, j = e & 127;
        int col = col0 + j, b = col >> 5, h = col & 31;
        sIdx[e] = idx[(((b << 8) + (chunk * 8 + w8)) << 5) + h];
    }
    __syncthreads();

    int jB = tid >> 2, cq = tid & 3;
    const float* h3b = h3t + ((size_t)((col0 + jB) >> 5) << 20);

    int kA = tid >> 5;
    int oA = (tid & 31) * 8;
    const float* abase = w8tt + (size_t)chunk * 2048 * 256;

    float acc[4][4][4] = {};
    float4 a0, a1, bv, scv, sfv;

    {
        const float* ap = abase + (size_t)kA * 256 + oA;
        a0 = *(const float4*)(ap);
        a1 = *(const float4*)(ap + 4);
        int n = sIdx[jB];
        bv  = *(const float4*)(h3b + ((size_t)n << 8) + cq * 4);
        scv = *(const float4*)(sc3 + cq * 4);
        sfv = *(const float4*)(sf3 + cq * 4);
    }
    {
        float* ar = &As[0][kA][oA];
        *(float4*)(ar)     = make_float4(f2tf32f(a0.x), f2tf32f(a0.y), f2tf32f(a0.z), f2tf32f(a0.w));
        *(float4*)(ar + 4) = make_float4(f2tf32f(a1.x), f2tf32f(a1.y), f2tf32f(a1.z), f2tf32f(a1.w));
        Bs[0][cq*4+0][jB] = f2tf32f(bv.x * scv.x + sfv.x);
        Bs[0][cq*4+1][jB] = f2tf32f(bv.y * scv.y + sfv.y);
        Bs[0][cq*4+2][jB] = f2tf32f(bv.z * scv.z + sfv.z);
        Bs[0][cq*4+3][jB] = f2tf32f(bv.w * scv.w + sfv.w);
    }
    __syncthreads();

    for (int t = 0; t < 128; t++) {
        int s = t & 1;
        bool more = (t < 127);
        if (more) {
            int t1 = t + 1;
            int w8 = t1 >> 4, c0 = (t1 & 15) * 16;
            const float* ap = abase + (size_t)(w8 * 256 + c0 + kA) * 256 + oA;
            a0 = *(const float4*)(ap);
            a1 = *(const float4*)(ap + 4);
            int n = sIdx[w8 * 128 + jB];
            bv  = *(const float4*)(h3b + ((size_t)n << 8) + c0 + cq * 4);
            scv = *(const float4*)(sc3 + c0 + cq * 4);
            sfv = *(const float4*)(sf3 + c0 + cq * 4);
        }

        #pragma unroll
        for (int ks = 0; ks < 2; ks++) {
            int kk = ks * 8;
            uint32_t a[4][4], bf[4][2];
            #pragma unroll
            for (int i = 0; i < 4; i++) {
                int mr = wm + i * 16 + gid;
                a[i][0] = __float_as_uint(As[s][kk + tig    ][mr    ]);
                a[i][1] = __float_as_uint(As[s][kk + tig    ][mr + 8]);
                a[i][2] = __float_as_uint(As[s][kk + tig + 4][mr    ]);
                a[i][3] = __float_as_uint(As[s][kk + tig + 4][mr + 8]);
            }
            #pragma unroll
            for (int j = 0; j < 4; j++) {
                int nc = wn + j * 8 + gid;
                bf[j][0] = __float_as_uint(Bs[s][kk + tig    ][nc]);
                bf[j][1] = __float_as_uint(Bs[s][kk + tig + 4][nc]);
            }
            #pragma unroll
            for (int i = 0; i < 4; i++)
                #pragma unroll
                for (int j = 0; j < 4; j++)
                    mma_tf32(acc[i][j], a[i], bf[j]);
        }

        if (more) {
            int d = s ^ 1;
            float* ar = &As[d][kA][oA];
            *(float4*)(ar)     = make_float4(f2tf32f(a0.x), f2tf32f(a0.y), f2tf32f(a0.z), f2tf32f(a0.w));
            *(float4*)(ar + 4) = make_float4(f2tf32f(a1.x), f2tf32f(a1.y), f2tf32f(a1.z), f2tf32f(a1.w));
            Bs[d][cq*4+0][jB] = f2tf32f(bv.x * scv.x + sfv.x);
            Bs[d][cq*4+1][jB] = f2tf32f(bv.y * scv.y + sfv.y);
            Bs[d][cq*4+2][jB] = f2tf32f(bv.z * scv.z + sfv.z);
            Bs[d][cq*4+3][jB] = f2tf32f(bv.w * scv.w + sfv.w);
        }
        __syncthreads();
    }

    #pragma unroll
    for (int i = 0; i < 4; i++) {
        int r0 = wm + i * 16 + gid;
        size_t base0 = ((size_t)chunk * 256 + r0) * 512 + col0;
        size_t base1 = ((size_t)chunk * 256 + r0 + 8) * 512 + col0;
        #pragma unroll
        for (int j = 0; j < 4; j++) {
            int c = wn + j * 8 + 2 * tig;
            *(float2*)&P8[base0 + c] = make_float2(acc[i][j][0], acc[i][j][1]);
            *(float2*)&P8[base1 + c] = make_float2(acc[i][j][2], acc[i][j][3]);
        }
    }
}

// ---------------- w8 transpose -----------------------------------------------------
__global__ void transpose_w8(const float* __restrict__ src, float* __restrict__ dst)
{
    __shared__ float s[32][33];
    int c = blockIdx.z, o0 = blockIdx.y * 32, w0 = blockIdx.x * 32;
    int tx = threadIdx.x, ty = threadIdx.y;
    #pragma unroll
    for (int k = 0; k < 4; k++)
        s[ty + 8 * k][tx] = src[(size_t)(o0 + ty + 8 * k) * 65536 + c * 256 + w0 + tx];
    __syncthreads();
    #pragma unroll
    for (int k = 0; k < 4; k++)
        dst[(size_t)(w0 + ty + 8 * k) * 65536 + c * 256 + o0 + tx] = s[tx][ty + 8 * k];
}

// ---------------- exact top-32 per (b,c) row — incremental ---------------------------
__global__ void topk_kernel(const float* __restrict__ X, int* __restrict__ idx_out)
{
    int bc = blockIdx.x;
    const float* row = X + (size_t)bc * NPTS;
    int tid  = threadIdx.x;
    int lane = tid & 31;
    int warp = tid >> 5;

    float v[16];
    #pragma unroll
    for (int j = 0; j < 16; j++) v[j] = row[j * 256 + tid];

    float lv = -FLT_MAX; int li = 0x7fffffff;
    #pragma unroll
    for (int j = 0; j < 16; j++) {
        int n = j * 256 + tid;
        if (v[j] > lv || (v[j] == lv && n < li)) { lv = v[j]; li = n; }
    }

    __shared__ float swv[8];
    __shared__ int   swi[8];
    __shared__ int   sbi;

    {
        float tv = lv; int ti = li;
        #pragma unroll
        for (int off = 16; off > 0; off >>= 1) {
            float ov = __shfl_down_sync(0xffffffff, tv, off);
            int   oi = __shfl_down_sync(0xffffffff, ti, off);
            if (ov > tv || (ov == tv && oi < ti)) { tv = ov; ti = oi; }
        }
        if (lane == 0) { swv[warp] = tv; swi[warp] = ti; }
    }
    __syncthreads();

    for (int iter = 0; iter < 32; iter++) {
        if (tid == 0) {
            float gv = swv[0]; int gi = swi[0];
            #pragma unroll
            for (int w = 1; w < 8; w++)
                if (swv[w] > gv || (swv[w] == gv && swi[w] < gi)) { gv = swv[w]; gi = swi[w]; }
            sbi = gi;
            idx_out[bc * 32 + iter] = gi;
        }
        __syncthreads();
        if (iter == 31) break;
        int gi = sbi;
        int ow = (gi & 255) >> 5;
        if ((gi & 255) == tid) {
            v[gi >> 8] = -FLT_MAX;
            lv = -FLT_MAX; li = 0x7fffffff;
            #pragma unroll
            for (int j = 0; j < 16; j++) {
                int n = j * 256 + tid;
                if (v[j] > lv || (v[j] == lv && n < li)) { lv = v[j]; li = n; }
            }
        }
        if (warp == ow) {
            float tv = lv; int ti = li;
            #pragma unroll
            for (int off = 16; off > 0; off >>= 1) {
                float ov = __shfl_down_sync(0xffffffff, tv, off);
                int   oi = __shfl_down_sync(0xffffffff, ti, off);
                if (ov > tv || (ov == tv && oi < ti)) { tv = ov; ti = oi; }
            }
            if (lane == 0) { swv[ow] = tv; swi[ow] = ti; }
        }
        __syncthreads();
    }
}

// ---------------- conv8 split-K reduce (32 chunks) ----------------------------------
__global__ void reduce8_kernel(const float* __restrict__ P, const float* __restrict__ b8,
                               float* __restrict__ y8)
{
    int i = blockIdx.x * blockDim.x + threadIdx.x;
    float s = b8[i >> 9];
    #pragma unroll
    for (int ch = 0; ch < 32; ch++) s += P[(size_t)ch * 131072 + i];
    y8[i] = s;
}

// ---------------- conv9 ------------------------------------------------------------
__global__ void conv9_kernel(const float* __restrict__ y8, const float* __restrict__ w9,
                             const float* __restrict__ b9, float* __restrict__ y9)
{
    int b = blockIdx.x >> 8;
    int o = blockIdx.x & 255;
    int c = threadIdx.x;
    float s = 0.f;
    const float* yb = y8 + (size_t)c * 512 + b * 32;
    const float* wr = w9 + ((size_t)o * 256 + c) * 32;
    #pragma unroll
    for (int h = 0; h < 32; h++) s += yb[h] * wr[h];
    __shared__ float sh[256];
    sh[c] = s; __syncthreads();
    for (int st = 128; st > 0; st >>= 1) {
        if (c < st) sh[c] += sh[c + st];
        __syncthreads();
    }
    if (c == 0) y9[b * 256 + o] = sh[0] + b9[o];
}

// ---------------- glob contribution to conv4 ---------------------------------------
__global__ void gcon_kernel(const float* __restrict__ w4, const float* __restrict__ y9,
                            float* __restrict__ gcon)
{
    int i = blockIdx.x * blockDim.x + threadIdx.x;
    int b = i >> 9, o = i & 511;
    float s = 0.f;
    for (int c = 0; c < 256; c++) s += w4[o * 320 + c] * y9[b * 256 + c];
    gcon[i] = s;
}

// ---------------- conv7 + bn6 + relu + tanh ----------------------------------------
__global__ void conv7_kernel(const float* __restrict__ h6, const float* __restrict__ sc,
                             const float* __restrict__ sf, const float* __restrict__ w7,
                             const float* __restrict__ b7, float* __restrict__ out)
{
    int i = blockIdx.x * blockDim.x + threadIdx.x;
    int b = i >> 12, n = i & (NPTS - 1);
    float s0 = b7[0], s1 = b7[1], s2 = b7[2];
    const float* hb = h6 + (((size_t)b * 128) << 12) + n;
    for (int c = 0; c < 128; c++) {
        float v = fmaxf(hb[(size_t)c * NPTS] * sc[c] + sf[c], 0.f);
        s0 += w7[c] * v;
        s1 += w7[128 + c] * v;
        s2 += w7[256 + c] * v;
    }
    out[((size_t)(b * 3 + 0)) * NPTS + n] = tanhf(s0);
    out[((size_t)(b * 3 + 1)) * NPTS + n] = tanhf(s1);
    out[((size_t)(b * 3 + 2)) * NPTS + n] = tanhf(s2);
}

// ===================================================================================
extern "C" void kernel_launch(void* const* d_in, const int* in_sizes, int n_in,
                              void* d_out, int out_size)
{
    const float* x   = (const float*)d_in[0];
    const float* w1  = (const float*)d_in[1];
    const float* b1  = (const float*)d_in[2];
    const float* g1  = (const float*)d_in[3];
    const float* be1 = (const float*)d_in[4];
    const float* w2  = (const float*)d_in[5];
    const float* b2  = (const float*)d_in[6];
    const float* g2  = (const float*)d_in[7];
    const float* be2 = (const float*)d_in[8];
    const float* w3  = (const float*)d_in[9];
    const float* b3  = (const float*)d_in[10];
    const float* g3  = (const float*)d_in[11];
    const float* be3 = (const float*)d_in[12];
    const float* w4  = (const float*)d_in[13];
    const float* b4  = (const float*)d_in[14];
    const float* g4  = (const float*)d_in[15];
    const float* be4 = (const float*)d_in[16];
    const float* w5  = (const float*)d_in[17];
    const float* b5  = (const float*)d_in[18];
    const float* g5  = (const float*)d_in[19];
    const float* be5 = (const float*)d_in[20];
    const float* w6  = (const float*)d_in[21];
    const float* b6  = (const float*)d_in[22];
    const float* g6  = (const float*)d_in[23];
    const float* be6 = (const float*)d_in[24];
    const float* w7  = (const float*)d_in[25];
    const float* b7  = (const float*)d_in[26];
    const float* w8  = (const float*)d_in[27];
    const float* b8  = (const float*)d_in[28];
    const float* w9  = (const float*)d_in[29];
    const float* b9  = (const float*)d_in[30];
    float* out = (float*)d_out;

    float *h1, *h2, *h3, *h3t, *h4, *h5, *h6, *w8t, *P8, *y8, *y9, *gcon, *scale, *shift;
    float *part2;
    int *idxp;
    cudaGetSymbolAddress((void**)&h1,    g_h1);
    cudaGetSymbolAddress((void**)&h2,    g_h2);
    cudaGetSymbolAddress((void**)&h3,    g_h3);
    cudaGetSymbolAddress((void**)&h3t,   g_h3t);
    cudaGetSymbolAddress((void**)&h4,    g_h4);
    cudaGetSymbolAddress((void**)&h5,    g_h5);
    cudaGetSymbolAddress((void**)&h6,    g_h6);
    cudaGetSymbolAddress((void**)&w8t,   g_w8t);
    cudaGetSymbolAddress((void**)&P8,    g_P8);
    cudaGetSymbolAddress((void**)&y8,    g_y8);
    cudaGetSymbolAddress((void**)&y9,    g_y9);
    cudaGetSymbolAddress((void**)&gcon,  g_gcon);
    cudaGetSymbolAddress((void**)&idxp,  g_idx);
    cudaGetSymbolAddress((void**)&scale, g_scale);
    cudaGetSymbolAddress((void**)&shift, g_shift);
    cudaGetSymbolAddress((void**)&part2, g_part2);

    float* sc1 = scale + 0 * 512; float* sf1 = shift + 0 * 512;
    float* sc2 = scale + 1 * 512; float* sf2 = shift + 1 * 512;
    float* sc3 = scale + 2 * 512; float* sf3 = shift + 2 * 512;
    float* sc4 = scale + 3 * 512; float* sf4 = shift + 3 * 512;
    float* sc5 = scale + 4 * 512; float* sf5 = shift + 4 * 512;
    float* sc6 = scale + 5 * 512; float* sf6 = shift + 5 * 512;

    // conv1 (4->64), raw out (exact fp32, tiny K); stats fused in epilogue
    gemm_f32<<<dim3(64, 1, B_), 256>>>(x, w1, b1, h1, 64, 4, NPTS, 4, nullptr, nullptr, 0,
                                       part2);
    stats_fin2<<<64, 256>>>(part2, 1024, g1, be1, sc1, sf1);

    // conv2 (64->128), bn1+relu fused; stats fused in epilogue
    gemm_f32_big<<<dim3(64, 1, B_), 256>>>(h1, w2, b2, h2, 128, 64, NPTS, 64, sc1, sf1, 1,
                                           nullptr, 0, part2);
    stats_fin2<<<128, 256>>>(part2, 1024, g2, be2, sc2, sf2);

    // conv3 (128->256), bn2+relu fused, dual-writes h3 and h3t; stats fused
    gemm_f32_big<<<dim3(64, 2, B_), 256>>>(h2, w3, b3, h3, 256, 128, NPTS, 128, sc2, sf2, 1,
                                           h3t, 256, part2);

    // top-32 on raw h3 (order preserved under positive BN scale)
    topk_kernel<<<B_ * 256, 256>>>(h3, idxp);

    stats_fin2<<<256, 256>>>(part2, 1024, g3, be3, sc3, sf3);
    transpose_w8<<<dim3(8, 8, 256), dim3(32, 8)>>>(w8, w8t);

    // conv8 fused gather GEMM (bn3 in gather), split-K 32, BM256xBN128, 128 CTAs
    conv8_kernel<<<dim3(4, 32), 512>>>(h3t, w8t, idxp, sc3, sf3, P8);
    reduce8_kernel<<<(256 * 512) / 256, 256>>>(P8, b8, y8);

    conv9_kernel<<<B_ * 256, 256>>>(y8, w9, b9, y9);
    gcon_kernel<<<(B_ * 512) / 256, 256>>>(w4, y9, gcon);

    // conv4 (64->512) tf32 128x128, bn1+relu fused, + gcon; stats fused
    gemm_tf32<<<dim3(32, 4, B_), 256>>>(h1, w4 + 256, b4, gcon, h4, 512, 64, NPTS, 320,
                                        sc1, sf1, 1, part2);
    stats_fin2<<<512, 256>>>(part2, 32 * B_, g4, be4, sc4, sf4);

    // conv5 (512->256) tf32 128x128, bn4+relu fused; stats fused
    gemm_tf32<<<dim3(32, 2, B_), 256>>>(h4, w5, b5, nullptr, h5, 256, 512, NPTS, 512,
                                        sc4, sf4, 1, part2);
    stats_fin2<<<256, 256>>>(part2, 32 * B_, g5, be5, sc5, sf5);

    // conv6 (256->128) tf32 128x128, bn5+relu fused; stats fused
    gemm_tf32<<<dim3(32, 1, B_), 256>>>(h5, w6, b6, nullptr, h6, 128, 256, NPTS, 256,
                                        sc5, sf5, 1, part2);
    stats_fin2<<<128, 256>>>(part2, 32 * B_, g6, be6, sc6, sf6);

    // conv7 (128->3) + bn6 + relu + tanh
    conv7_kernel<<<(B_ * NPTS) / 256, 256>>>(h6, sc6, sf6, w7, b7, out);
}

// round 17
// speedup vs baseline: 1.0777x; 1.0438x over previous
#include <cuda_runtime.h>
#include <cuda_fp16.h>
#include <math.h>
#include <float.h>
#include <stdint.h>

#define B_    16
#define NPTS  4096

// ---------------- scratch (static device globals) ---------------------------------
__device__ float g_h1[(size_t)B_ * 64  * NPTS];
__device__ float g_h2[(size_t)B_ * 128 * NPTS];
__device__ float g_h3[(size_t)B_ * 256 * NPTS];
__device__ float g_h3t[(size_t)B_ * NPTS * 256];   // [b][n][c]
__device__ float g_h4[(size_t)B_ * 512 * NPTS];
__device__ float g_h5[(size_t)B_ * 256 * NPTS];
__device__ float g_h6[(size_t)B_ * 128 * NPTS];
__device__ float g_w8t[(size_t)256 * 256 * 256];   // [w][c][o]
__device__ float g_P8[(size_t)32 * 256 * 512];     // split-K partials for conv8 (32 chunks)
__device__ float g_y8[256 * 512];                  // conv8 out, [o][b*32+h]
__device__ float g_y9[B_ * 512];
__device__ float g_gcon[B_ * 512];
__device__ int   g_idx[B_ * 256 * 32];
__device__ float g_scale[6 * 512];
__device__ float g_shift[6 * 512];
__device__ float g_part2[(size_t)512 * 1024 * 2];  // epilogue stats partials [c][slot][2]

__device__ __forceinline__ float f2tf32f(float f) {
    uint32_t u;
    asm("cvt.rna.tf32.f32 %0, %1;" : "=r"(u) : "f"(f));
    return __uint_as_float(u);
}

__device__ __forceinline__ void mma_tf32(float* d, const uint32_t* a, const uint32_t* b) {
    asm volatile(
        "mma.sync.aligned.m16n8k8.row.col.f32.tf32.tf32.f32 "
        "{%0,%1,%2,%3}, {%4,%5,%6,%7}, {%8,%9}, {%0,%1,%2,%3};"
        : "+f"(d[0]), "+f"(d[1]), "+f"(d[2]), "+f"(d[3])
        : "r"(a[0]), "r"(a[1]), "r"(a[2]), "r"(a[3]), "r"(b[0]), "r"(b[1]));
}

__device__ __forceinline__ void mma_f16(float* d, const uint32_t* a, const uint32_t* b) {
    asm volatile(
        "mma.sync.aligned.m16n8k16.row.col.f32.f16.f16.f32 "
        "{%0,%1,%2,%3}, {%4,%5,%6,%7}, {%8,%9}, {%0,%1,%2,%3};"
        : "+f"(d[0]), "+f"(d[1]), "+f"(d[2]), "+f"(d[3])
        : "r"(a[0]), "r"(a[1]), "r"(a[2]), "r"(a[3]), "r"(b[0]), "r"(b[1]));
}

__device__ __forceinline__ void bn4(float4& v, float sc, float sf, int relu) {
    v.x = v.x * sc + sf; v.y = v.y * sc + sf;
    v.z = v.z * sc + sf; v.w = v.w * sc + sf;
    if (relu) {
        v.x = fmaxf(v.x, 0.f); v.y = fmaxf(v.y, 0.f);
        v.z = fmaxf(v.z, 0.f); v.w = fmaxf(v.w, 0.f);
    }
}

// ---------------- fp32 SGEMM 64x64 (conv1 only: K=4) + fused stats ------------------
__global__ void gemm_f32(const float* __restrict__ X, const float* __restrict__ W,
                         const float* __restrict__ bias, float* __restrict__ Y,
                         int O, int K, int N, int ldw,
                         const float* __restrict__ bnS, const float* __restrict__ bnF,
                         int relu, float* __restrict__ statPart)
{
    __shared__ float As[16][66];
    __shared__ float Bs[16][64];

    int b  = blockIdx.z;
    int o0 = blockIdx.y * 64;
    int n0 = blockIdx.x * 64;
    const float* Xb = X + (size_t)b * K * N;

    int tid = threadIdx.x;
    int tm  = tid >> 4;
    int tn  = tid & 15;

    float acc[4][4] = {};

    for (int k0 = 0; k0 < K; k0 += 16) {
        #pragma unroll
        for (int i = 0; i < 4; i++) {
            int e = tid + i * 256;
            int m = e >> 4, k = e & 15;
            As[k][m] = (k0 + k < K) ? W[(size_t)(o0 + m) * ldw + k0 + k] : 0.f;
        }
        #pragma unroll
        for (int i = 0; i < 4; i++) {
            int e = tid + i * 256;
            int k = e >> 6, n = e & 63;
            float v = 0.f;
            if (k0 + k < K) {
                v = Xb[(size_t)(k0 + k) * N + n0 + n];
                if (bnS) {
                    v = v * bnS[k0 + k] + bnF[k0 + k];
                    if (relu) v = fmaxf(v, 0.f);
                }
            }
            Bs[k][n] = v;
        }
        __syncthreads();
        #pragma unroll
        for (int kk = 0; kk < 16; kk++) {
            float a[4], bb[4];
            #pragma unroll
            for (int i = 0; i < 4; i++) a[i]  = As[kk][tm * 4 + i];
            #pragma unroll
            for (int j = 0; j < 4; j++) bb[j] = Bs[kk][tn * 4 + j];
            #pragma unroll
            for (int i = 0; i < 4; i++)
                #pragma unroll
                for (int j = 0; j < 4; j++)
                    acc[i][j] += a[i] * bb[j];
        }
        __syncthreads();
    }

    #pragma unroll
    for (int i = 0; i < 4; i++) {
        int o = o0 + tm * 4 + i;
        float bv = bias ? bias[o] : 0.f;
        #pragma unroll
        for (int j = 0; j < 4; j++) acc[i][j] += bv;
        size_t base = (size_t)(b * O + o) * N;
        *(float4*)&Y[base + n0 + tn * 4] =
            make_float4(acc[i][0], acc[i][1], acc[i][2], acc[i][3]);
    }

    if (statPart) {
        int slot = blockIdx.x + gridDim.x * b;   // 64*16 = 1024 slots
        #pragma unroll
        for (int i = 0; i < 4; i++) {
            float s = acc[i][0] + acc[i][1] + acc[i][2] + acc[i][3];
            float q = acc[i][0] * acc[i][0] + acc[i][1] * acc[i][1]
                    + acc[i][2] * acc[i][2] + acc[i][3] * acc[i][3];
            #pragma unroll
            for (int off = 8; off > 0; off >>= 1) {
                s += __shfl_down_sync(0xffffffff, s, off, 16);
                q += __shfl_down_sync(0xffffffff, q, off, 16);
            }
            if (tn == 0) {
                int o = o0 + tm * 4 + i;
                statPart[((size_t)o * 1024 + slot) * 2 + 0] = s;
                statPart[((size_t)o * 1024 + slot) * 2 + 1] = q;
            }
        }
    }
}

// ---------------- fp32 SGEMM 128x64, 8x4 micro, double-buffered (conv2, conv3) -----
__global__ void __launch_bounds__(256) gemm_f32_big(
    const float* __restrict__ X, const float* __restrict__ W,
    const float* __restrict__ bias, float* __restrict__ Y,
    int O, int K, int N, int ldw,
    const float* __restrict__ bnS, const float* __restrict__ bnF, int relu,
    float* __restrict__ Yt, int Ct, float* __restrict__ statPart)
{
    __shared__ float As[2][16][132];
    __shared__ float Bs[2][16][68];

    int b  = blockIdx.z;
    int o0 = blockIdx.y * 128;
    int n0 = blockIdx.x * 64;
    const float* Xb = X + (size_t)b * K * N;

    int tid = threadIdx.x;
    int tm  = tid >> 4;
    int tn  = tid & 15;

    int rowA = tid & 127;
    int kqA  = tid >> 7;
    const float* wp = W + (size_t)(o0 + rowA) * ldw;
    int krB = tid >> 4;
    int n4  = (tid & 15) * 4;

    float acc[8][4] = {};
    float4 ra0, ra1, rb;

    {
        ra0 = *(const float4*)(wp + kqA * 4);
        ra1 = *(const float4*)(wp + (kqA + 2) * 4);
        rb  = *(const float4*)(Xb + (size_t)krB * N + n0 + n4);
        As[0][kqA * 4 + 0][rowA] = ra0.x;
        As[0][kqA * 4 + 1][rowA] = ra0.y;
        As[0][kqA * 4 + 2][rowA] = ra0.z;
        As[0][kqA * 4 + 3][rowA] = ra0.w;
        As[0][(kqA + 2) * 4 + 0][rowA] = ra1.x;
        As[0][(kqA + 2) * 4 + 1][rowA] = ra1.y;
        As[0][(kqA + 2) * 4 + 2][rowA] = ra1.z;
        As[0][(kqA + 2) * 4 + 3][rowA] = ra1.w;
        float4 v = rb;
        if (bnS) bn4(v, bnS[krB], bnF[krB], relu);
        *(float4*)&Bs[0][krB][n4] = v;
    }
    __syncthreads();

    int nIter = K / 16;
    for (int it = 0; it < nIter; it++) {
        int s = it & 1;
        bool more = (it + 1 < nIter);
        if (more) {
            int k0 = (it + 1) * 16;
            ra0 = *(const float4*)(wp + k0 + kqA * 4);
            ra1 = *(const float4*)(wp + k0 + (kqA + 2) * 4);
            rb  = *(const float4*)(Xb + (size_t)(k0 + krB) * N + n0 + n4);
        }

        #pragma unroll
        for (int kk = 0; kk < 16; kk++) {
            float a[8], bb[4];
            *(float4*)&a[0] = *(const float4*)&As[s][kk][tm * 8];
            *(float4*)&a[4] = *(const float4*)&As[s][kk][tm * 8 + 4];
            *(float4*)&bb[0] = *(const float4*)&Bs[s][kk][tn * 4];
            #pragma unroll
            for (int i = 0; i < 8; i++)
                #pragma unroll
                for (int j = 0; j < 4; j++)
                    acc[i][j] += a[i] * bb[j];
        }

        if (more) {
            int d = s ^ 1;
            As[d][kqA * 4 + 0][rowA] = ra0.x;
            As[d][kqA * 4 + 1][rowA] = ra0.y;
            As[d][kqA * 4 + 2][rowA] = ra0.z;
            As[d][kqA * 4 + 3][rowA] = ra0.w;
            As[d][(kqA + 2) * 4 + 0][rowA] = ra1.x;
            As[d][(kqA + 2) * 4 + 1][rowA] = ra1.y;
            As[d][(kqA + 2) * 4 + 2][rowA] = ra1.z;
            As[d][(kqA + 2) * 4 + 3][rowA] = ra1.w;
            float4 v = rb;
            if (bnS) bn4(v, bnS[(it + 1) * 16 + krB], bnF[(it + 1) * 16 + krB], relu);
            *(float4*)&Bs[d][krB][n4] = v;
        }
        __syncthreads();
    }

    #pragma unroll
    for (int i = 0; i < 8; i++) {
        int o = o0 + tm * 8 + i;
        float bv = bias ? bias[o] : 0.f;
        #pragma unroll
        for (int j = 0; j < 4; j++) acc[i][j] += bv;
        *(float4*)&Y[(size_t)(b * O + o) * N + n0 + tn * 4] =
            make_float4(acc[i][0], acc[i][1], acc[i][2], acc[i][3]);
    }

    if (statPart) {
        int slot = blockIdx.x + gridDim.x * b;
        #pragma unroll
        for (int i = 0; i < 8; i++) {
            float s = acc[i][0] + acc[i][1] + acc[i][2] + acc[i][3];
            float q = acc[i][0] * acc[i][0] + acc[i][1] * acc[i][1]
                    + acc[i][2] * acc[i][2] + acc[i][3] * acc[i][3];
            #pragma unroll
            for (int off = 8; off > 0; off >>= 1) {
                s += __shfl_down_sync(0xffffffff, s, off, 16);
                q += __shfl_down_sync(0xffffffff, q, off, 16);
            }
            if (tn == 0) {
                int o = o0 + tm * 8 + i;
                statPart[((size_t)o * 1024 + slot) * 2 + 0] = s;
                statPart[((size_t)o * 1024 + slot) * 2 + 1] = q;
            }
        }
    }

    if (Yt) {
        float* stage = &As[0][0][0];
        #pragma unroll
        for (int h = 0; h < 2; h++) {
            __syncthreads();
            if ((tn >> 3) == h) {
                int nb = (tn & 7) * 4;
                #pragma unroll
                for (int j = 0; j < 4; j++)
                    #pragma unroll
                    for (int i = 0; i < 8; i++)
                        stage[(nb + j) * 132 + tm * 8 + i] = acc[i][j];
            }
            __syncthreads();
            int nn0 = tid >> 5;
            int c4  = (tid & 31) * 4;
            #pragma unroll
            for (int r = 0; r < 4; r++) {
                int nn = nn0 + r * 8;
                float4 v = *(float4*)&stage[nn * 132 + c4];
                *(float4*)&Yt[((size_t)b * NPTS + n0 + h * 32 + nn) * (size_t)Ct + o0 + c4] = v;
            }
        }
    }
}

// ---------------- fp16 GEMM, 128x128 tile, 256 thr, warp 32x64 (conv4/5/6) ---------
// Same structure as the settled tf32 kernel; k packed in __half2 pairs, m16n8k16.
__global__ void __launch_bounds__(256) gemm_f16(
    const float* __restrict__ X, const float* __restrict__ W,
    const float* __restrict__ bias, const float* __restrict__ biasBO,
    float* __restrict__ Y, int O, int K, int N, int ldw,
    const float* __restrict__ bnS, const float* __restrict__ bnF, int relu,
    float* __restrict__ statPart)
{
    __shared__ __half2 As[2][8][136];   // [k-pair][m]
    __shared__ __half2 Bs[2][8][136];   // [k-pair][n]

    int b  = blockIdx.z;
    int o0 = blockIdx.y * 128;
    int n0 = blockIdx.x * 128;
    const float* Xb = X + (size_t)b * K * N;

    int tid  = threadIdx.x;
    int lane = tid & 31;
    int warp = tid >> 5;
    int wm   = (warp & 3) * 32;
    int wn_i = warp >> 2;
    int wn   = wn_i * 64;
    int gid  = lane >> 2;
    int tig  = lane & 3;

    int rowA = tid & 127;
    int kqA  = tid >> 7;               // 0/1: k 0..3,8..11 or 4..7,12..15
    const float* wp = W + (size_t)(o0 + rowA) * ldw;
    int krB = tid >> 5;                // 0..7 -> k rows 2*krB, 2*krB+1
    int n4  = (tid & 31) * 4;

    float acc[2][8][4] = {};
    float4 ra0, ra1, rb0, rb1;

    {
        ra0 = *(const float4*)(wp + kqA * 4);
        ra1 = *(const float4*)(wp + kqA * 4 + 8);
        rb0 = *(const float4*)(Xb + (size_t)(2 * krB)     * N + n0 + n4);
        rb1 = *(const float4*)(Xb + (size_t)(2 * krB + 1) * N + n0 + n4);
        if (bnS) {
            bn4(rb0, bnS[2 * krB],     bnF[2 * krB],     relu);
            bn4(rb1, bnS[2 * krB + 1], bnF[2 * krB + 1], relu);
        }
        As[0][kqA * 2 + 0][rowA] = __floats2half2_rn(ra0.x, ra0.y);
        As[0][kqA * 2 + 1][rowA] = __floats2half2_rn(ra0.z, ra0.w);
        As[0][kqA * 2 + 4][rowA] = __floats2half2_rn(ra1.x, ra1.y);
        As[0][kqA * 2 + 5][rowA] = __floats2half2_rn(ra1.z, ra1.w);
        Bs[0][krB][n4 + 0] = __floats2half2_rn(rb0.x, rb1.x);
        Bs[0][krB][n4 + 1] = __floats2half2_rn(rb0.y, rb1.y);
        Bs[0][krB][n4 + 2] = __floats2half2_rn(rb0.z, rb1.z);
        Bs[0][krB][n4 + 3] = __floats2half2_rn(rb0.w, rb1.w);
    }
    __syncthreads();

    int nIter = K / 16;
    for (int it = 0; it < nIter; it++) {
        int s = it & 1;
        bool more = (it + 1 < nIter);
        if (more) {
            int k0 = (it + 1) * 16;
            ra0 = *(const float4*)(wp + k0 + kqA * 4);
            ra1 = *(const float4*)(wp + k0 + kqA * 4 + 8);
            rb0 = *(const float4*)(Xb + (size_t)(k0 + 2 * krB)     * N + n0 + n4);
            rb1 = *(const float4*)(Xb + (size_t)(k0 + 2 * krB + 1) * N + n0 + n4);
            if (bnS) {
                bn4(rb0, bnS[k0 + 2 * krB],     bnF[k0 + 2 * krB],     relu);
                bn4(rb1, bnS[k0 + 2 * krB + 1], bnF[k0 + 2 * krB + 1], relu);
            }
        }

        {
            uint32_t a[2][4], bf[8][2];
            #pragma unroll
            for (int i = 0; i < 2; i++) {
                int mr = wm + i * 16 + gid;
                a[i][0] = *(const uint32_t*)&As[s][tig    ][mr    ];
                a[i][1] = *(const uint32_t*)&As[s][tig    ][mr + 8];
                a[i][2] = *(const uint32_t*)&As[s][tig + 4][mr    ];
                a[i][3] = *(const uint32_t*)&As[s][tig + 4][mr + 8];
            }
            #pragma unroll
            for (int j = 0; j < 8; j++) {
                int nc = wn + j * 8 + gid;
                bf[j][0] = *(const uint32_t*)&Bs[s][tig    ][nc];
                bf[j][1] = *(const uint32_t*)&Bs[s][tig + 4][nc];
            }
            #pragma unroll
            for (int i = 0; i < 2; i++)
                #pragma unroll
                for (int j = 0; j < 8; j++)
                    mma_f16(acc[i][j], a[i], bf[j]);
        }

        if (more) {
            int d = s ^ 1;
            As[d][kqA * 2 + 0][rowA] = __floats2half2_rn(ra0.x, ra0.y);
            As[d][kqA * 2 + 1][rowA] = __floats2half2_rn(ra0.z, ra0.w);
            As[d][kqA * 2 + 4][rowA] = __floats2half2_rn(ra1.x, ra1.y);
            As[d][kqA * 2 + 5][rowA] = __floats2half2_rn(ra1.z, ra1.w);
            Bs[d][krB][n4 + 0] = __floats2half2_rn(rb0.x, rb1.x);
            Bs[d][krB][n4 + 1] = __floats2half2_rn(rb0.y, rb1.y);
            Bs[d][krB][n4 + 2] = __floats2half2_rn(rb0.z, rb1.z);
            Bs[d][krB][n4 + 3] = __floats2half2_rn(rb0.w, rb1.w);
        }
        __syncthreads();
    }

    float rsum[2][2], rsq[2][2];

    #pragma unroll
    for (int i = 0; i < 2; i++) {
        int r0 = o0 + wm + i * 16 + gid;
        int r1 = r0 + 8;
        float bv0 = 0.f, bv1 = 0.f;
        if (bias)   { bv0 += bias[r0]; bv1 += bias[r1]; }
        if (biasBO) { bv0 += biasBO[b * O + r0]; bv1 += biasBO[b * O + r1]; }
        size_t base0 = (size_t)(b * O + r0) * N;
        size_t base1 = (size_t)(b * O + r1) * N;
        float s0 = 0.f, s1 = 0.f, q0 = 0.f, q1 = 0.f;
        #pragma unroll
        for (int j = 0; j < 8; j++) {
            int c = n0 + wn + j * 8 + 2 * tig;
            float v00 = acc[i][j][0] + bv0, v01 = acc[i][j][1] + bv0;
            float v10 = acc[i][j][2] + bv1, v11 = acc[i][j][3] + bv1;
            *(float2*)&Y[base0 + c] = make_float2(v00, v01);
            *(float2*)&Y[base1 + c] = make_float2(v10, v11);
            s0 += v00 + v01; q0 += v00 * v00 + v01 * v01;
            s1 += v10 + v11; q1 += v10 * v10 + v11 * v11;
        }
        rsum[i][0] = s0; rsum[i][1] = s1;
        rsq[i][0]  = q0; rsq[i][1]  = q1;
    }

    if (statPart) {
        float* rs = (float*)&As[0][0][0];
        #pragma unroll
        for (int i = 0; i < 2; i++) {
            #pragma unroll
            for (int r = 0; r < 2; r++) {
                float s = rsum[i][r], q = rsq[i][r];
                #pragma unroll
                for (int off = 2; off > 0; off >>= 1) {
                    s += __shfl_down_sync(0xffffffff, s, off, 4);
                    q += __shfl_down_sync(0xffffffff, q, off, 4);
                }
                if (tig == 0) {
                    int row = wm + i * 16 + gid + r * 8;
                    rs[(row * 2 + wn_i) * 2 + 0] = s;
                    rs[(row * 2 + wn_i) * 2 + 1] = q;
                }
            }
        }
        __syncthreads();
        if (tid < 128) {
            float s = rs[(tid * 2 + 0) * 2 + 0] + rs[(tid * 2 + 1) * 2 + 0];
            float q = rs[(tid * 2 + 0) * 2 + 1] + rs[(tid * 2 + 1) * 2 + 1];
            int o = o0 + tid;
            int slot = blockIdx.x + gridDim.x * b;
            statPart[((size_t)o * 1024 + slot) * 2 + 0] = s;
            statPart[((size_t)o * 1024 + slot) * 2 + 1] = q;
        }
    }
}

// ---------------- epilogue-stats finalize -------------------------------------------
__global__ void stats_fin2(const float* __restrict__ part2, int nslots,
                           const float* __restrict__ g, const float* __restrict__ be,
                           float* __restrict__ scale, float* __restrict__ shift)
{
    int c = blockIdx.x;
    float s = 0.f, q = 0.f;
    for (int t = threadIdx.x; t < nslots; t += 256) {
        s += part2[((size_t)c * 1024 + t) * 2 + 0];
        q += part2[((size_t)c * 1024 + t) * 2 + 1];
    }
    __shared__ float sh1[256], sh2[256];
    sh1[threadIdx.x] = s; sh2[threadIdx.x] = q;
    __syncthreads();
    for (int st = 128; st > 0; st >>= 1) {
        if (threadIdx.x < st) {
            sh1[threadIdx.x] += sh1[threadIdx.x + st];
            sh2[threadIdx.x] += sh2[threadIdx.x + st];
        }
        __syncthreads();
    }
    if (threadIdx.x == 0) {
        const float inv = 1.f / (float)(B_ * NPTS);
        float m  = sh1[0] * inv;
        float v  = sh2[0] * inv - m * m;
        float sc = g[c] / sqrtf(v + 1e-5f);
        scale[c] = sc;
        shift[c] = be[c] - m * sc;
    }
}

// ---------------- conv8 fused gather GEMM (512 thr, BM=256 x BN=128, split-K 32) ---
__global__ void __launch_bounds__(512) conv8_kernel(
    const float* __restrict__ h3t, const float* __restrict__ w8tt,
    const int* __restrict__ idx, const float* __restrict__ sc3,
    const float* __restrict__ sf3, float* __restrict__ P8)
{
    __shared__ float As[2][16][264];
    __shared__ float Bs[2][16][136];
    __shared__ int   sIdx[1024];

    int col0  = blockIdx.x * 128;
    int chunk = blockIdx.y;
    int tid = threadIdx.x;
    int lane = tid & 31, warp = tid >> 5;
    int wm = (warp & 3) * 64;
    int wn = (warp >> 2) * 32;
    int gid = lane >> 2, tig = lane & 3;

    #pragma unroll
    for (int i = 0; i < 2; i++) {
        int e = tid + i * 512;
        int w8 = e >> 7, j = e & 127;
        int col = col0 + j, b = col >> 5, h = col & 31;
        sIdx[e] = idx[(((b << 8) + (chunk * 8 + w8)) << 5) + h];
    }
    __syncthreads();

    int jB = tid >> 2, cq = tid & 3;
    const float* h3b = h3t + ((size_t)((col0 + jB) >> 5) << 20);

    int kA = tid >> 5;
    int oA = (tid & 31) * 8;
    const float* abase = w8tt + (size_t)chunk * 2048 * 256;

    float acc[4][4][4] = {};
    float4 a0, a1, bv, scv, sfv;

    {
        const float* ap = abase + (size_t)kA * 256 + oA;
        a0 = *(const float4*)(ap);
        a1 = *(const float4*)(ap + 4);
        int n = sIdx[jB];
        bv  = *(const float4*)(h3b + ((size_t)n << 8) + cq * 4);
        scv = *(const float4*)(sc3 + cq * 4);
        sfv = *(const float4*)(sf3 + cq * 4);
    }
    {
        float* ar = &As[0][kA][oA];
        *(float4*)(ar)     = make_float4(f2tf32f(a0.x), f2tf32f(a0.y), f2tf32f(a0.z), f2tf32f(a0.w));
        *(float4*)(ar + 4) = make_float4(f2tf32f(a1.x), f2tf32f(a1.y), f2tf32f(a1.z), f2tf32f(a1.w));
        Bs[0][cq*4+0][jB] = f2tf32f(bv.x * scv.x + sfv.x);
        Bs[0][cq*4+1][jB] = f2tf32f(bv.y * scv.y + sfv.y);
        Bs[0][cq*4+2][jB] = f2tf32f(bv.z * scv.z + sfv.z);
        Bs[0][cq*4+3][jB] = f2tf32f(bv.w * scv.w + sfv.w);
    }
    __syncthreads();

    for (int t = 0; t < 128; t++) {
        int s = t & 1;
        bool more = (t < 127);
        if (more) {
            int t1 = t + 1;
            int w8 = t1 >> 4, c0 = (t1 & 15) * 16;
            const float* ap = abase + (size_t)(w8 * 256 + c0 + kA) * 256 + oA;
            a0 = *(const float4*)(ap);
            a1 = *(const float4*)(ap + 4);
            int n = sIdx[w8 * 128 + jB];
            bv  = *(const float4*)(h3b + ((size_t)n << 8) + c0 + cq * 4);
            scv = *(const float4*)(sc3 + c0 + cq * 4);
            sfv = *(const float4*)(sf3 + c0 + cq * 4);
        }

        #pragma unroll
        for (int ks = 0; ks < 2; ks++) {
            int kk = ks * 8;
            uint32_t a[4][4], bf[4][2];
            #pragma unroll
            for (int i = 0; i < 4; i++) {
                int mr = wm + i * 16 + gid;
                a[i][0] = __float_as_uint(As[s][kk + tig    ][mr    ]);
                a[i][1] = __float_as_uint(As[s][kk + tig    ][mr + 8]);
                a[i][2] = __float_as_uint(As[s][kk + tig + 4][mr    ]);
                a[i][3] = __float_as_uint(As[s][kk + tig + 4][mr + 8]);
            }
            #pragma unroll
            for (int j = 0; j < 4; j++) {
                int nc = wn + j * 8 + gid;
                bf[j][0] = __float_as_uint(Bs[s][kk + tig    ][nc]);
                bf[j][1] = __float_as_uint(Bs[s][kk + tig + 4][nc]);
            }
            #pragma unroll
            for (int i = 0; i < 4; i++)
                #pragma unroll
                for (int j = 0; j < 4; j++)
                    mma_tf32(acc[i][j], a[i], bf[j]);
        }

        if (more) {
            int d = s ^ 1;
            float* ar = &As[d][kA][oA];
            *(float4*)(ar)     = make_float4(f2tf32f(a0.x), f2tf32f(a0.y), f2tf32f(a0.z), f2tf32f(a0.w));
            *(float4*)(ar + 4) = make_float4(f2tf32f(a1.x), f2tf32f(a1.y), f2tf32f(a1.z), f2tf32f(a1.w));
            Bs[d][cq*4+0][jB] = f2tf32f(bv.x * scv.x + sfv.x);
            Bs[d][cq*4+1][jB] = f2tf32f(bv.y * scv.y + sfv.y);
            Bs[d][cq*4+2][jB] = f2tf32f(bv.z * scv.z + sfv.z);
            Bs[d][cq*4+3][jB] = f2tf32f(bv.w * scv.w + sfv.w);
        }
        __syncthreads();
    }

    #pragma unroll
    for (int i = 0; i < 4; i++) {
        int r0 = wm + i * 16 + gid;
        size_t base0 = ((size_t)chunk * 256 + r0) * 512 + col0;
        size_t base1 = ((size_t)chunk * 256 + r0 + 8) * 512 + col0;
        #pragma unroll
        for (int j = 0; j < 4; j++) {
            int c = wn + j * 8 + 2 * tig;
            *(float2*)&P8[base0 + c] = make_float2(acc[i][j][0], acc[i][j][1]);
            *(float2*)&P8[base1 + c] = make_float2(acc[i][j][2], acc[i][j][3]);
        }
    }
}

// ---------------- w8 transpose -----------------------------------------------------
__global__ void transpose_w8(const float* __restrict__ src, float* __restrict__ dst)
{
    __shared__ float s[32][33];
    int c = blockIdx.z, o0 = blockIdx.y * 32, w0 = blockIdx.x * 32;
    int tx = threadIdx.x, ty = threadIdx.y;
    #pragma unroll
    for (int k = 0; k < 4; k++)
        s[ty + 8 * k][tx] = src[(size_t)(o0 + ty + 8 * k) * 65536 + c * 256 + w0 + tx];
    __syncthreads();
    #pragma unroll
    for (int k = 0; k < 4; k++)
        dst[(size_t)(w0 + ty + 8 * k) * 65536 + c * 256 + o0 + tx] = s[tx][ty + 8 * k];
}

// ---------------- exact top-32 per (b,c) row — incremental ---------------------------
__global__ void topk_kernel(const float* __restrict__ X, int* __restrict__ idx_out)
{
    int bc = blockIdx.x;
    const float* row = X + (size_t)bc * NPTS;
    int tid  = threadIdx.x;
    int lane = tid & 31;
    int warp = tid >> 5;

    float v[16];
    #pragma unroll
    for (int j = 0; j < 16; j++) v[j] = row[j * 256 + tid];

    float lv = -FLT_MAX; int li = 0x7fffffff;
    #pragma unroll
    for (int j = 0; j < 16; j++) {
        int n = j * 256 + tid;
        if (v[j] > lv || (v[j] == lv && n < li)) { lv = v[j]; li = n; }
    }

    __shared__ float swv[8];
    __shared__ int   swi[8];
    __shared__ int   sbi;

    {
        float tv = lv; int ti = li;
        #pragma unroll
        for (int off = 16; off > 0; off >>= 1) {
            float ov = __shfl_down_sync(0xffffffff, tv, off);
            int   oi = __shfl_down_sync(0xffffffff, ti, off);
            if (ov > tv || (ov == tv && oi < ti)) { tv = ov; ti = oi; }
        }
        if (lane == 0) { swv[warp] = tv; swi[warp] = ti; }
    }
    __syncthreads();

    for (int iter = 0; iter < 32; iter++) {
        if (tid == 0) {
            float gv = swv[0]; int gi = swi[0];
            #pragma unroll
            for (int w = 1; w < 8; w++)
                if (swv[w] > gv || (swv[w] == gv && swi[w] < gi)) { gv = swv[w]; gi = swi[w]; }
            sbi = gi;
            idx_out[bc * 32 + iter] = gi;
        }
        __syncthreads();
        if (iter == 31) break;
        int gi = sbi;
        int ow = (gi & 255) >> 5;
        if ((gi & 255) == tid) {
            v[gi >> 8] = -FLT_MAX;
            lv = -FLT_MAX; li = 0x7fffffff;
            #pragma unroll
            for (int j = 0; j < 16; j++) {
                int n = j * 256 + tid;
                if (v[j] > lv || (v[j] == lv && n < li)) { lv = v[j]; li = n; }
            }
        }
        if (warp == ow) {
            float tv = lv; int ti = li;
            #pragma unroll
            for (int off = 16; off > 0; off >>= 1) {
                float ov = __shfl_down_sync(0xffffffff, tv, off);
                int   oi = __shfl_down_sync(0xffffffff, ti, off);
                if (ov > tv || (ov == tv && oi < ti)) { tv = ov; ti = oi; }
            }
            if (lane == 0) { swv[ow] = tv; swi[ow] = ti; }
        }
        __syncthreads();
    }
}

// ---------------- conv8 split-K reduce (32 chunks) ----------------------------------
__global__ void reduce8_kernel(const float* __restrict__ P, const float* __restrict__ b8,
                               float* __restrict__ y8)
{
    int i = blockIdx.x * blockDim.x + threadIdx.x;
    float s = b8[i >> 9];
    #pragma unroll
    for (int ch = 0; ch < 32; ch++) s += P[(size_t)ch * 131072 + i];
    y8[i] = s;
}

// ---------------- conv9 ------------------------------------------------------------
__global__ void conv9_kernel(const float* __restrict__ y8, const float* __restrict__ w9,
                             const float* __restrict__ b9, float* __restrict__ y9)
{
    int b = blockIdx.x >> 8;
    int o = blockIdx.x & 255;
    int c = threadIdx.x;
    float s = 0.f;
    const float* yb = y8 + (size_t)c * 512 + b * 32;
    const float* wr = w9 + ((size_t)o * 256 + c) * 32;
    #pragma unroll
    for (int h = 0; h < 32; h++) s += yb[h] * wr[h];
    __shared__ float sh[256];
    sh[c] = s; __syncthreads();
    for (int st = 128; st > 0; st >>= 1) {
        if (c < st) sh[c] += sh[c + st];
        __syncthreads();
    }
    if (c == 0) y9[b * 256 + o] = sh[0] + b9[o];
}

// ---------------- glob contribution to conv4 ---------------------------------------
__global__ void gcon_kernel(const float* __restrict__ w4, const float* __restrict__ y9,
                            float* __restrict__ gcon)
{
    int i = blockIdx.x * blockDim.x + threadIdx.x;
    int b = i >> 9, o = i & 511;
    float s = 0.f;
    for (int c = 0; c < 256; c++) s += w4[o * 320 + c] * y9[b * 256 + c];
    gcon[i] = s;
}

// ---------------- conv7 + bn6 + relu + tanh ----------------------------------------
__global__ void conv7_kernel(const float* __restrict__ h6, const float* __restrict__ sc,
                             const float* __restrict__ sf, const float* __restrict__ w7,
                             const float* __restrict__ b7, float* __restrict__ out)
{
    int i = blockIdx.x * blockDim.x + threadIdx.x;
    int b = i >> 12, n = i & (NPTS - 1);
    float s0 = b7[0], s1 = b7[1], s2 = b7[2];
    const float* hb = h6 + (((size_t)b * 128) << 12) + n;
    for (int c = 0; c < 128; c++) {
        float v = fmaxf(hb[(size_t)c * NPTS] * sc[c] + sf[c], 0.f);
        s0 += w7[c] * v;
        s1 += w7[128 + c] * v;
        s2 += w7[256 + c] * v;
    }
    out[((size_t)(b * 3 + 0)) * NPTS + n] = tanhf(s0);
    out[((size_t)(b * 3 + 1)) * NPTS + n] = tanhf(s1);
    out[((size_t)(b * 3 + 2)) * NPTS + n] = tanhf(s2);
}

// ===================================================================================
extern "C" void kernel_launch(void* const* d_in, const int* in_sizes, int n_in,
                              void* d_out, int out_size)
{
    const float* x   = (const float*)d_in[0];
    const float* w1  = (const float*)d_in[1];
    const float* b1  = (const float*)d_in[2];
    const float* g1  = (const float*)d_in[3];
    const float* be1 = (const float*)d_in[4];
    const float* w2  = (const float*)d_in[5];
    const float* b2  = (const float*)d_in[6];
    const float* g2  = (const float*)d_in[7];
    const float* be2 = (const float*)d_in[8];
    const float* w3  = (const float*)d_in[9];
    const float* b3  = (const float*)d_in[10];
    const float* g3  = (const float*)d_in[11];
    const float* be3 = (const float*)d_in[12];
    const float* w4  = (const float*)d_in[13];
    const float* b4  = (const float*)d_in[14];
    const float* g4  = (const float*)d_in[15];
    const float* be4 = (const float*)d_in[16];
    const float* w5  = (const float*)d_in[17];
    const float* b5  = (const float*)d_in[18];
    const float* g5  = (const float*)d_in[19];
    const float* be5 = (const float*)d_in[20];
    const float* w6  = (const float*)d_in[21];
    const float* b6  = (const float*)d_in[22];
    const float* g6  = (const float*)d_in[23];
    const float* be6 = (const float*)d_in[24];
    const float* w7  = (const float*)d_in[25];
    const float* b7  = (const float*)d_in[26];
    const float* w8  = (const float*)d_in[27];
    const float* b8  = (const float*)d_in[28];
    const float* w9  = (const float*)d_in[29];
    const float* b9  = (const float*)d_in[30];
    float* out = (float*)d_out;

    float *h1, *h2, *h3, *h3t, *h4, *h5, *h6, *w8t, *P8, *y8, *y9, *gcon, *scale, *shift;
    float *part2;
    int *idxp;
    cudaGetSymbolAddress((void**)&h1,    g_h1);
    cudaGetSymbolAddress((void**)&h2,    g_h2);
    cudaGetSymbolAddress((void**)&h3,    g_h3);
    cudaGetSymbolAddress((void**)&h3t,   g_h3t);
    cudaGetSymbolAddress((void**)&h4,    g_h4);
    cudaGetSymbolAddress((void**)&h5,    g_h5);
    cudaGetSymbolAddress((void**)&h6,    g_h6);
    cudaGetSymbolAddress((void**)&w8t,   g_w8t);
    cudaGetSymbolAddress((void**)&P8,    g_P8);
    cudaGetSymbolAddress((void**)&y8,    g_y8);
    cudaGetSymbolAddress((void**)&y9,    g_y9);
    cudaGetSymbolAddress((void**)&gcon,  g_gcon);
    cudaGetSymbolAddress((void**)&idxp,  g_idx);
    cudaGetSymbolAddress((void**)&scale, g_scale);
    cudaGetSymbolAddress((void**)&shift, g_shift);
    cudaGetSymbolAddress((void**)&part2, g_part2);

    float* sc1 = scale + 0 * 512; float* sf1 = shift + 0 * 512;
    float* sc2 = scale + 1 * 512; float* sf2 = shift + 1 * 512;
    float* sc3 = scale + 2 * 512; float* sf3 = shift + 2 * 512;
    float* sc4 = scale + 3 * 512; float* sf4 = shift + 3 * 512;
    float* sc5 = scale + 4 * 512; float* sf5 = shift + 4 * 512;
    float* sc6 = scale + 5 * 512; float* sf6 = shift + 5 * 512;

    // conv1 (4->64), raw out (exact fp32, tiny K); stats fused in epilogue
    gemm_f32<<<dim3(64, 1, B_), 256>>>(x, w1, b1, h1, 64, 4, NPTS, 4, nullptr, nullptr, 0,
                                       part2);
    stats_fin2<<<64, 256>>>(part2, 1024, g1, be1, sc1, sf1);

    // conv2 (64->128), bn1+relu fused; stats fused in epilogue
    gemm_f32_big<<<dim3(64, 1, B_), 256>>>(h1, w2, b2, h2, 128, 64, NPTS, 64, sc1, sf1, 1,
                                           nullptr, 0, part2);
    stats_fin2<<<128, 256>>>(part2, 1024, g2, be2, sc2, sf2);

    // conv3 (128->256), bn2+relu fused, dual-writes h3 and h3t; stats fused
    gemm_f32_big<<<dim3(64, 2, B_), 256>>>(h2, w3, b3, h3, 256, 128, NPTS, 128, sc2, sf2, 1,
                                           h3t, 256, part2);

    // top-32 on raw h3 (order preserved under positive BN scale)
    topk_kernel<<<B_ * 256, 256>>>(h3, idxp);

    stats_fin2<<<256, 256>>>(part2, 1024, g3, be3, sc3, sf3);
    transpose_w8<<<dim3(8, 8, 256), dim3(32, 8)>>>(w8, w8t);

    // conv8 fused gather GEMM (bn3 in gather), split-K 32, BM256xBN128, 128 CTAs
    conv8_kernel<<<dim3(4, 32), 512>>>(h3t, w8t, idxp, sc3, sf3, P8);
    reduce8_kernel<<<(256 * 512) / 256, 256>>>(P8, b8, y8);

    conv9_kernel<<<B_ * 256, 256>>>(y8, w9, b9, y9);
    gcon_kernel<<<(B_ * 512) / 256, 256>>>(w4, y9, gcon);

    // conv4 (64->512) fp16 mma 128x128, bn1+relu fused, + gcon; stats fused
    gemm_f16<<<dim3(32, 4, B_), 256>>>(h1, w4 + 256, b4, gcon, h4, 512, 64, NPTS, 320,
                                       sc1, sf1, 1, part2);
    stats_fin2<<<512, 256>>>(part2, 32 * B_, g4, be4, sc4, sf4);

    // conv5 (512->256) fp16 mma 128x128, bn4+relu fused; stats fused
    gemm_f16<<<dim3(32, 2, B_), 256>>>(h4, w5, b5, nullptr, h5, 256, 512, NPTS, 512,
                                       sc4, sf4, 1, part2);
    stats_fin2<<<256, 256>>>(part2, 32 * B_, g5, be5, sc5, sf5);

    // conv6 (256->128) fp16 mma 128x128, bn5+relu fused; stats fused
    gemm_f16<<<dim3(32, 1, B_), 256>>>(h5, w6, b6, nullptr, h6, 128, 256, NPTS, 256,
                                       sc5, sf5, 1, part2);
    stats_fin2<<<128, 256>>>(part2, 32 * B_, g6, be6, sc6, sf6);

    // conv7 (128->3) + bn6 + relu + tanh
    conv7_kernel<<<(B_ * NPTS) / 256, 256>>>(h6, sc6, sf6, w7, b7, out);
}